// round 1
// baseline (speedup 1.0000x reference)
#include <cuda_runtime.h>

#define Tt   12
#define Nn   100000
#define CINc 16
#define Ee   20000
#define NNZn 160000
#define Hh   64
#define Pp   12

// ---------------- scratch (device globals; no allocation in kernel_launch) ----
__device__ float g_xs[(size_t)Tt * Nn * Hh];      // h2 per t (final node emb)
__device__ float g_h1[(size_t)Tt * Nn * Hh];      // layer-1 node accum
__device__ float g_xw[(size_t)Tt * Nn * Hh];      // xw1 then xw2 (reused)
__device__ float g_es[(size_t)Tt * Ee * Hh];      // e2 per t (final edge emb)
__device__ float g_edge1[(size_t)Tt * Ee * Hh];   // layer-1 edge accum
__device__ float g_agg[(size_t)Hh * Nn * 9];      // Agg_flat (c,n,s) order
__device__ float g_eagg[(size_t)Hh * Ee * 9];     // Eagg_flat (c,e,s) order
__device__ float g_dinv[Tt * Nn];
__device__ float g_binv[Tt * Ee];
__device__ float g_wm1t[576 * Hh];                // Wm1 transposed [64][576]

// ---------------- zero accumulators ----------------
__global__ void k_zero() {
    size_t i = (size_t)blockIdx.x * blockDim.x + threadIdx.x;
    size_t stride = (size_t)gridDim.x * blockDim.x;
    const float4 z4 = make_float4(0.f, 0.f, 0.f, 0.f);
    const size_t n1 = (size_t)Tt * Nn * Hh / 4;
    for (size_t j = i; j < n1; j += stride) { ((float4*)g_xs)[j] = z4; ((float4*)g_h1)[j] = z4; }
    const size_t n2 = (size_t)Tt * Ee * Hh / 4;
    for (size_t j = i; j < n2; j += stride) { ((float4*)g_es)[j] = z4; ((float4*)g_edge1)[j] = z4; }
    const size_t n3 = Tt * Nn / 4;
    for (size_t j = i; j < n3; j += stride) ((float4*)g_dinv)[j] = z4;
    const size_t n4 = Tt * Ee / 4;
    for (size_t j = i; j < n4; j += stride) ((float4*)g_binv)[j] = z4;
}

// ---------------- degrees (counts into g_dinv/g_binv) ----------------
__global__ void k_deg(const int* __restrict__ ni, const int* __restrict__ ei) {
    int i = blockIdx.x * blockDim.x + threadIdx.x;
    if (i >= Tt * NNZn) return;
    int t = i / NNZn;
    atomicAdd(&g_dinv[t * Nn + ni[i]], 1.f);
    atomicAdd(&g_binv[t * Ee + ei[i]], 1.f);
}

__global__ void k_inv() {
    int i = blockIdx.x * blockDim.x + threadIdx.x;
    if (i < Tt * Nn) { float d = g_dinv[i]; g_dinv[i] = d > 0.f ? rsqrtf(d) : 0.f; }
    if (i < Tt * Ee) { float c = g_binv[i]; g_binv[i] = c > 0.f ? 1.f / c : 0.f; }
}

// ---------------- xw1 = x @ W1 + b1 ----------------
__global__ void k_xw1(const float* __restrict__ nf, const float* __restrict__ W1,
                      const float* __restrict__ b1) {
    __shared__ float sW[CINc * Hh];
    int tid = threadIdx.x;
    for (int j = tid; j < CINc * Hh; j += 256) sW[j] = W1[j];
    __syncthreads();
    int u = blockIdx.x * 4 + (tid >> 6);
    int h = tid & 63;
    if (u >= Tt * Nn) return;
    const float4* x4 = (const float4*)(nf + (size_t)u * CINc);
    float xv[16];
#pragma unroll
    for (int c4 = 0; c4 < 4; c4++) {
        float4 v = x4[c4];
        xv[c4 * 4 + 0] = v.x; xv[c4 * 4 + 1] = v.y; xv[c4 * 4 + 2] = v.z; xv[c4 * 4 + 3] = v.w;
    }
    float acc = b1[h];
#pragma unroll
    for (int c = 0; c < CINc; c++) acc = fmaf(xv[c], sW[c * Hh + h], acc);
    g_xw[(size_t)u * Hh + h] = acc;
}

// ---------------- xw2 = (h1*dinv) @ W2 + b2 ----------------
__global__ void k_xw2(const float* __restrict__ W2, const float* __restrict__ b2) {
    __shared__ float sW[Hh * Hh];
    int tid = threadIdx.x;
    for (int j = tid; j < Hh * Hh; j += 256) sW[j] = W2[j];
    __syncthreads();
    int u = blockIdx.x * 4 + (tid >> 6);
    int h = tid & 63;
    if (u >= Tt * Nn) return;
    const float4* hr4 = (const float4*)(g_h1 + (size_t)u * Hh);
    float acc = 0.f;
#pragma unroll
    for (int c4 = 0; c4 < Hh / 4; c4++) {
        float4 v = hr4[c4];
        acc = fmaf(v.x, sW[(c4 * 4 + 0) * Hh + h], acc);
        acc = fmaf(v.y, sW[(c4 * 4 + 1) * Hh + h], acc);
        acc = fmaf(v.z, sW[(c4 * 4 + 2) * Hh + h], acc);
        acc = fmaf(v.w, sW[(c4 * 4 + 3) * Hh + h], acc);
    }
    g_xw[(size_t)u * Hh + h] = fmaf(g_dinv[u], acc, b2[h]);
}

// ---------------- scatter: edge[e] += xw[n]*dinv[n]   MODE 0 -> g_edge1, 1 -> g_es
template <int MODE>
__global__ void k_scatter(const int* __restrict__ ni, const int* __restrict__ ei) {
    int gi = blockIdx.x * blockDim.x + threadIdx.x;
    if (gi >= Tt * NNZn * 16) return;
    int k = gi >> 4, q = gi & 15;
    int t = k / NNZn;
    int n = ni[k], e = ei[k];
    float d = g_dinv[t * Nn + n];
    float4 v = *(const float4*)(g_xw + (size_t)(t * Nn + n) * Hh + q * 4);
    v.x *= d; v.y *= d; v.z *= d; v.w *= d;
    float* dst = (MODE == 0 ? g_edge1 : g_es) + (size_t)(t * Ee + e) * Hh + q * 4;
    atomicAdd((float4*)dst, v);
}

// ---------------- gather: node[n] += edge[e]*(binv)   MODE 0: edge1*binv -> h1, 1: es -> xs
template <int MODE>
__global__ void k_gather(const int* __restrict__ ni, const int* __restrict__ ei) {
    int gi = blockIdx.x * blockDim.x + threadIdx.x;
    if (gi >= Tt * NNZn * 16) return;
    int k = gi >> 4, q = gi & 15;
    int t = k / NNZn;
    int n = ni[k], e = ei[k];
    float s = (MODE == 0) ? g_binv[t * Ee + e] : 1.f;
    const float* src = (MODE == 0 ? g_edge1 : g_es) + (size_t)(t * Ee + e) * Hh + q * 4;
    float4 v = *(const float4*)src;
    v.x *= s; v.y *= s; v.z *= s; v.w *= s;
    float* dst = (MODE == 0 ? g_h1 : g_xs) + (size_t)(t * Nn + n) * Hh + q * 4;
    atomicAdd((float4*)dst, v);
}

// ---------------- row scale:  MODE 0: es *= binv, MODE 1: xs *= dinv ----------------
template <int MODE>
__global__ void k_scale() {
    int gi = blockIdx.x * blockDim.x + threadIdx.x;
    const int rows = (MODE == 0) ? Tt * Ee : Tt * Nn;
    if (gi >= rows * 16) return;
    int r = gi >> 4, q = gi & 15;
    float s = (MODE == 0) ? g_binv[r] : g_dinv[r];
    float4* p = (float4*)((MODE == 0 ? g_es : g_xs) + (size_t)r * Hh) + q;
    float4 v = *p;
    v.x *= s; v.y *= s; v.z *= s; v.w *= s;
    *p = v;
}

// ---------------- per-node: aggregator conv + indiv_logit (only channels 61..63 needed)
__global__ void k_node(const float* __restrict__ nf,
                       const float* __restrict__ Wna, const float* __restrict__ bna,
                       const float* __restrict__ Wt,  const float* __restrict__ bt,
                       const float* __restrict__ Wr,  const float* __restrict__ br,
                       const float* __restrict__ Wf,  const float* __restrict__ bf,
                       float* __restrict__ out) {
    __shared__ float sh[Tt][Hh];
    __shared__ float shv[3][Tt];
    int n = blockIdx.x;
    int c = threadIdx.x;  // 64 threads
#pragma unroll
    for (int t = 0; t < Tt; t++) sh[t][c] = g_xs[((size_t)t * Nn + n) * Hh + c];
    __syncthreads();

    // --- node aggregator: agg(c,n,s) = bna[c] + sum_i sum_dk Wna[c,i,dk]*xs[s+dk,n,i]
    float acc[9];
#pragma unroll
    for (int s = 0; s < 9; s++) acc[s] = bna[c];
    const float* w = Wna + c * Hh * 3;
#pragma unroll 4
    for (int i = 0; i < Hh; i++) {
        float w0 = w[i * 3], w1 = w[i * 3 + 1], w2 = w[i * 3 + 2];
        float xv[11];
#pragma unroll
        for (int tau = 0; tau < 11; tau++) xv[tau] = sh[tau][i];
#pragma unroll
        for (int s = 0; s < 9; s++)
            acc[s] = fmaf(w0, xv[s], fmaf(w1, xv[s + 1], fmaf(w2, xv[s + 2], acc[s])));
    }
    size_t base = ((size_t)c * Nn + n) * 9;
#pragma unroll
    for (int s = 0; s < 9; s++) g_agg[base + s] = acc[s];

    // --- indiv logit: temporal conv (ch 61..63 only) + residual + relu + final conv
    if (c < 36) {
        int o3 = c / Tt, t = c % Tt;
        int o = 61 + o3;
        float xp = bt[o];
#pragma unroll
        for (int dk = 0; dk < 3; dk++) {
            int tau = t + dk - 1;
            if (tau >= 0 && tau < Tt) {
                const float* wt = Wt + o * Hh * 3 + dk;
#pragma unroll 8
                for (int i = 0; i < Hh; i++) xp = fmaf(wt[i * 3], sh[tau][i], xp);
            }
        }
        float rs = br[o];
        const float* xr = nf + ((size_t)t * Nn + n) * CINc;
#pragma unroll
        for (int cc = 0; cc < CINc; cc++) rs = fmaf(Wr[o * CINc + cc], xr[cc], rs);
        shv[o3][t] = fmaxf(xp + rs, 0.f);
    }
    __syncthreads();
    if (c < Pp) {
        float a = bf[c];
#pragma unroll
        for (int t = 0; t < Tt; t++)
#pragma unroll
            for (int dk = 0; dk < 3; dk++)
                a = fmaf(Wf[c * Tt * 3 + t * 3 + dk], shv[dk][t], a);
        out[(size_t)n * Pp + c] = a;
    }
}

// ---------------- per-edge aggregator conv ----------------
__global__ void k_eagg(const float* __restrict__ Wea, const float* __restrict__ bea) {
    __shared__ float sh[11][Hh];
    int e = blockIdx.x;
    int c = threadIdx.x;
#pragma unroll
    for (int t = 0; t < 11; t++) sh[t][c] = g_es[((size_t)t * Ee + e) * Hh + c];
    __syncthreads();
    float acc[9];
#pragma unroll
    for (int s = 0; s < 9; s++) acc[s] = bea[c];
    const float* w = Wea + c * Hh * 3;
#pragma unroll 4
    for (int i = 0; i < Hh; i++) {
        float w0 = w[i * 3], w1 = w[i * 3 + 1], w2 = w[i * 3 + 2];
        float xv[11];
#pragma unroll
        for (int tau = 0; tau < 11; tau++) xv[tau] = sh[tau][i];
#pragma unroll
        for (int s = 0; s < 9; s++)
            acc[s] = fmaf(w0, xv[s], fmaf(w1, xv[s + 1], fmaf(w2, xv[s + 2], acc[s])));
    }
    size_t base = ((size_t)c * Ee + e) * 9;
#pragma unroll
    for (int s = 0; s < 9; s++) g_eagg[base + s] = acc[s];
}

// ---------------- Wm1 transpose ----------------
__global__ void k_wm1t(const float* __restrict__ Wm1) {
    int i = blockIdx.x * blockDim.x + threadIdx.x;
    if (i >= 576 * Hh) return;
    g_wm1t[(i & 63) * 576 + (i >> 6)] = Wm1[i];
}

// ---------------- score MLP: 4 pairs per block, 64 threads (thread = hidden unit)
__global__ void k_mlp(const int* __restrict__ ni_full, const int* __restrict__ ei_full,
                      const int* __restrict__ nni, const int* __restrict__ nei,
                      const float* __restrict__ bm1, const float* __restrict__ Wm2,
                      const float* __restrict__ bm2, float* __restrict__ out) {
    __shared__ float4 z[4][144];
    __shared__ float red[4][2];
    int tid = threadIdx.x;
    int q0 = blockIdx.x * 4;
#pragma unroll
    for (int p = 0; p < 4; p++) {
        int q = q0 + p;
        int n, e;
        if (q < NNZn) { n = ni_full[11 * NNZn + q]; e = ei_full[11 * NNZn + q]; }
        else          { n = nni[q - NNZn];          e = nei[q - NNZn]; }
        const float4* ar = (const float4*)(g_agg + (size_t)n * 576);
        const float4* er = (const float4*)(g_eagg + (size_t)e * 576);
        for (int j = tid; j < 144; j += 64) {
            float4 a = ar[j], b = er[j];
            z[p][j] = make_float4(a.x * b.x, a.y * b.y, a.z * b.z, a.w * b.w);
        }
    }
    __syncthreads();
    int h = tid;
    float a0 = bm1[h], a1 = a0, a2 = a0, a3 = a0;
    const float4* wt = (const float4*)(g_wm1t + (size_t)h * 576);
#pragma unroll 4
    for (int j = 0; j < 144; j++) {
        float4 wv = wt[j];
        float4 z0 = z[0][j], z1 = z[1][j], z2 = z[2][j], z3 = z[3][j];
        a0 = fmaf(wv.x, z0.x, a0); a0 = fmaf(wv.y, z0.y, a0); a0 = fmaf(wv.z, z0.z, a0); a0 = fmaf(wv.w, z0.w, a0);
        a1 = fmaf(wv.x, z1.x, a1); a1 = fmaf(wv.y, z1.y, a1); a1 = fmaf(wv.z, z1.z, a1); a1 = fmaf(wv.w, z1.w, a1);
        a2 = fmaf(wv.x, z2.x, a2); a2 = fmaf(wv.y, z2.y, a2); a2 = fmaf(wv.z, z2.z, a2); a2 = fmaf(wv.w, z2.w, a2);
        a3 = fmaf(wv.x, z3.x, a3); a3 = fmaf(wv.y, z3.y, a3); a3 = fmaf(wv.z, z3.z, a3); a3 = fmaf(wv.w, z3.w, a3);
    }
    float wm2h = Wm2[h];
    float r0 = fmaxf(a0, 0.f) * wm2h;
    float r1 = fmaxf(a1, 0.f) * wm2h;
    float r2 = fmaxf(a2, 0.f) * wm2h;
    float r3 = fmaxf(a3, 0.f) * wm2h;
#pragma unroll
    for (int off = 16; off; off >>= 1) {
        r0 += __shfl_down_sync(0xffffffffu, r0, off);
        r1 += __shfl_down_sync(0xffffffffu, r1, off);
        r2 += __shfl_down_sync(0xffffffffu, r2, off);
        r3 += __shfl_down_sync(0xffffffffu, r3, off);
    }
    if ((tid & 31) == 0) {
        int wgi = tid >> 5;
        red[0][wgi] = r0; red[1][wgi] = r1; red[2][wgi] = r2; red[3][wgi] = r3;
    }
    __syncthreads();
    if (tid < 4) {
        float v = red[tid][0] + red[tid][1] + bm2[0];
        out[(size_t)Nn * Pp + q0 + tid] = v;
    }
}

// ---------------- host launcher (graph-capturable, allocation-free) ----------------
extern "C" void kernel_launch(void* const* d_in, const int* in_sizes, int n_in,
                              void* d_out, int out_size) {
    const float* nf  = (const float*)d_in[0];
    const float* W1  = (const float*)d_in[1];
    const float* b1  = (const float*)d_in[2];
    const float* W2  = (const float*)d_in[3];
    const float* b2  = (const float*)d_in[4];
    const float* Wt  = (const float*)d_in[5];
    const float* bt  = (const float*)d_in[6];
    const float* Wr  = (const float*)d_in[7];
    const float* br  = (const float*)d_in[8];
    const float* Wf  = (const float*)d_in[9];
    const float* bf  = (const float*)d_in[10];
    const float* Wna = (const float*)d_in[11];
    const float* bna = (const float*)d_in[12];
    const float* Wea = (const float*)d_in[13];
    const float* bea = (const float*)d_in[14];
    const float* Wm1 = (const float*)d_in[15];
    const float* bm1 = (const float*)d_in[16];
    const float* Wm2 = (const float*)d_in[17];
    const float* bm2 = (const float*)d_in[18];
    const int* node_idx = (const int*)d_in[19];
    const int* edge_idx = (const int*)d_in[20];
    const int* nni = (const int*)d_in[21];
    const int* nei = (const int*)d_in[22];
    float* out = (float*)d_out;

    k_zero<<<8192, 256>>>();
    k_deg<<<(Tt * NNZn + 255) / 256, 256>>>(node_idx, edge_idx);
    k_inv<<<(Tt * Nn + 255) / 256, 256>>>();

    // layer 1
    k_xw1<<<(Tt * Nn + 3) / 4, 256>>>(nf, W1, b1);
    k_scatter<0><<<(Tt * NNZn * 16 + 255) / 256, 256>>>(node_idx, edge_idx);
    k_gather<0><<<(Tt * NNZn * 16 + 255) / 256, 256>>>(node_idx, edge_idx);

    // layer 2
    k_xw2<<<(Tt * Nn + 3) / 4, 256>>>(W2, b2);
    k_scatter<1><<<(Tt * NNZn * 16 + 255) / 256, 256>>>(node_idx, edge_idx);
    k_scale<0><<<(Tt * Ee * 16 + 255) / 256, 256>>>();   // es *= binv  (e2 final)
    k_gather<1><<<(Tt * NNZn * 16 + 255) / 256, 256>>>(node_idx, edge_idx);
    k_scale<1><<<(Tt * Nn * 16 + 255) / 256, 256>>>();   // xs *= dinv  (h2 final)

    // heads
    k_wm1t<<<(576 * Hh + 255) / 256, 256>>>(Wm1);
    k_node<<<Nn, 64>>>(nf, Wna, bna, Wt, bt, Wr, br, Wf, bf, out);
    k_eagg<<<Ee, 64>>>(Wea, bea);
    k_mlp<<<(2 * NNZn) / 4, 64>>>(node_idx, edge_idx, nni, nei, bm1, Wm2, bm2, out);
}

// round 3
// speedup vs baseline: 1.0358x; 1.0358x over previous
#include <cuda_runtime.h>

#define Tt   12
#define Nn   100000
#define CINc 16
#define Ee   20000
#define NNZn 160000
#define Hh   64
#define Pp   12

#define TN   (Tt * Nn)      // 1,200,000
#define TE   (Tt * Ee)      // 240,000
#define TNNZ (Tt * NNZn)    // 1,920,000

// ---------------- scratch (device globals; no allocation in kernel_launch) ----
__device__ float g_xs[(size_t)TN * Hh];        // h2 per t (final node emb)
__device__ float g_h1[(size_t)TN * Hh];        // layer-1 node output
__device__ float g_xw[(size_t)TN * Hh];        // xw*dinv (layer 1 then layer 2)
__device__ float g_es[(size_t)TE * Hh];        // e2 per t (final edge emb)
__device__ float g_edge1[(size_t)TE * Hh];     // layer-1 edge accum
__device__ float g_agg[(size_t)Hh * Nn * 9];   // Agg_flat (c,n,s) order
__device__ float g_eagg[(size_t)Hh * Ee * 9];  // Eagg_flat (c,e,s) order
__device__ float g_dinv[TN];
__device__ float g_binv[TE];
__device__ float g_wm1t[576 * Hh];             // Wm1 transposed [64][576]

// CSR scratch
__device__ int g_degN[TN];
__device__ int g_degE[TE];
__device__ int g_offN[TN + 1];
__device__ int g_offE[TE + 1];
__device__ int g_curN[TN];
__device__ int g_curE[TE];
__device__ int g_nlist[TNNZ];   // for each node slot: member edge ids
__device__ int g_elist[TNNZ];   // for each edge slot: member node ids
__device__ int g_part[1024];

// ---------------- zero (counts + cursors only; small) ----------------
__global__ void k_zero() {
    int i = blockIdx.x * blockDim.x + threadIdx.x;
    int stride = gridDim.x * blockDim.x;
    for (int j = i; j < TN; j += stride) { g_degN[j] = 0; g_curN[j] = 0; }
    for (int j = i; j < TE; j += stride) { g_degE[j] = 0; g_curE[j] = 0; }
}

// ---------------- degree counts ----------------
__global__ void k_count(const int* __restrict__ ni, const int* __restrict__ ei) {
    int i = blockIdx.x * blockDim.x + threadIdx.x;
    if (i >= TNNZ) return;
    int t = i / NNZn;
    atomicAdd(&g_degN[t * Nn + ni[i]], 1);
    atomicAdd(&g_degE[t * Ee + ei[i]], 1);
}

__global__ void k_inv() {
    int i = blockIdx.x * blockDim.x + threadIdx.x;
    if (i < TN) { int d = g_degN[i]; g_dinv[i] = d > 0 ? rsqrtf((float)d) : 0.f; }
    if (i < TE) { int c = g_degE[i]; g_binv[i] = c > 0 ? 1.f / (float)c : 0.f; }
}

// ---------------- 3-kernel exclusive scan, SEL=0: edges(TE), SEL=1: nodes(TN) ----
// All arrays referenced as device globals INSIDE device code (never passed from host).
template <int SEL>
__global__ void k_scanA() {
    const int* cnt = SEL ? g_degN : g_degE;
    const int n = SEL ? TN : TE;
    __shared__ int sh[256];
    int b = blockIdx.x, t = threadIdx.x;
    int i0 = b * 4096 + t * 16;
    int s = 0;
#pragma unroll
    for (int k = 0; k < 16; k++) { int i = i0 + k; if (i < n) s += cnt[i]; }
    sh[t] = s; __syncthreads();
    for (int off = 128; off; off >>= 1) {
        if (t < off) sh[t] += sh[t + off];
        __syncthreads();
    }
    if (t == 0) g_part[b] = sh[0];
}

__global__ void k_scanB(int nb) {
    __shared__ int sh[1024];
    int t = threadIdx.x;
    int v = (t < nb) ? g_part[t] : 0;
    sh[t] = v; __syncthreads();
    for (int off = 1; off < 1024; off <<= 1) {
        int a = (t >= off) ? sh[t - off] : 0;
        __syncthreads();
        sh[t] += a;
        __syncthreads();
    }
    if (t < nb) g_part[t] = sh[t] - v;  // exclusive
}

template <int SEL>
__global__ void k_scanC() {
    const int* cnt = SEL ? g_degN : g_degE;
    int* off = SEL ? g_offN : g_offE;
    const int n = SEL ? TN : TE;
    __shared__ int sh[256];
    int b = blockIdx.x, t = threadIdx.x;
    int i0 = b * 4096 + t * 16;
    int loc[16]; int s = 0;
#pragma unroll
    for (int k = 0; k < 16; k++) {
        int i = i0 + k;
        loc[k] = (i < n) ? cnt[i] : 0;
        s += loc[k];
    }
    sh[t] = s; __syncthreads();
    for (int o = 1; o < 256; o <<= 1) {
        int a = (t >= o) ? sh[t - o] : 0;
        __syncthreads();
        sh[t] += a;
        __syncthreads();
    }
    int run = g_part[b] + sh[t] - s;   // exclusive prefix for this thread's chunk
#pragma unroll
    for (int k = 0; k < 16; k++) {
        int i = i0 + k;
        if (i < n) {
            off[i] = run;
            run += loc[k];
            if (i == n - 1) off[n] = run;
        }
    }
}

// ---------------- fill CSR lists ----------------
__global__ void k_fill(const int* __restrict__ ni, const int* __restrict__ ei) {
    int i = blockIdx.x * blockDim.x + threadIdx.x;
    if (i >= TNNZ) return;
    int t = i / NNZn;
    int n = ni[i], e = ei[i];
    int se = t * Ee + e, sn = t * Nn + n;
    int pe = atomicAdd(&g_curE[se], 1);
    g_elist[g_offE[se] + pe] = n;
    int pn = atomicAdd(&g_curN[sn], 1);
    g_nlist[g_offN[sn] + pn] = e;
}

// ---------------- xw1 = (x @ W1 + b1) * dinv ----------------
__global__ void k_xw1(const float* __restrict__ nf, const float* __restrict__ W1,
                      const float* __restrict__ b1) {
    __shared__ float4 sW[16 * 16];   // [c][c4]
    __shared__ float sb[64];
    int tid = threadIdx.x;
    sW[tid] = ((const float4*)W1)[tid];
    if (tid < 64) sb[tid] = b1[tid];
    __syncthreads();
    int u = blockIdx.x * 16 + (tid >> 4);
    int c4 = tid & 15;
    if (u >= TN) return;
    float d = g_dinv[u];
    const float4* x4 = (const float4*)(nf + (size_t)u * CINc);
    float xv[16];
#pragma unroll
    for (int q = 0; q < 4; q++) {
        float4 v = x4[q];
        xv[q * 4 + 0] = v.x; xv[q * 4 + 1] = v.y; xv[q * 4 + 2] = v.z; xv[q * 4 + 3] = v.w;
    }
    float4 acc = make_float4(sb[c4 * 4], sb[c4 * 4 + 1], sb[c4 * 4 + 2], sb[c4 * 4 + 3]);
#pragma unroll
    for (int c = 0; c < 16; c++) {
        float4 w = sW[c * 16 + c4];
        float x = xv[c];
        acc.x = fmaf(x, w.x, acc.x); acc.y = fmaf(x, w.y, acc.y);
        acc.z = fmaf(x, w.z, acc.z); acc.w = fmaf(x, w.w, acc.w);
    }
    acc.x *= d; acc.y *= d; acc.z *= d; acc.w *= d;
    ((float4*)g_xw)[(size_t)u * 16 + c4] = acc;
}

// ---------------- xw2 = (h1 @ W2 + b2) * dinv ----------------
__global__ void k_xw2(const float* __restrict__ W2, const float* __restrict__ b2) {
    __shared__ float4 sW[64 * 16];   // [c][c4], 16KB
    __shared__ float sX[16][65];
    __shared__ float sb[64];
    int tid = threadIdx.x;
    for (int j = tid; j < 64 * 16; j += 256) sW[j] = ((const float4*)W2)[j];
    if (tid < 64) sb[tid] = b2[tid];
    int u0 = blockIdx.x * 16;
    {
        int g = tid >> 4, k = tid & 15;
        int u = u0 + g;
        float4 v = (u < TN) ? ((const float4*)g_h1)[(size_t)u * 16 + k]
                            : make_float4(0.f, 0.f, 0.f, 0.f);
        sX[g][k * 4 + 0] = v.x; sX[g][k * 4 + 1] = v.y;
        sX[g][k * 4 + 2] = v.z; sX[g][k * 4 + 3] = v.w;
    }
    __syncthreads();
    int g = tid >> 4, c4 = tid & 15;
    int u = u0 + g;
    if (u >= TN) return;
    float4 acc = make_float4(sb[c4 * 4], sb[c4 * 4 + 1], sb[c4 * 4 + 2], sb[c4 * 4 + 3]);
#pragma unroll 8
    for (int c = 0; c < 64; c++) {
        float4 w = sW[c * 16 + c4];
        float x = sX[g][c];
        acc.x = fmaf(x, w.x, acc.x); acc.y = fmaf(x, w.y, acc.y);
        acc.z = fmaf(x, w.z, acc.z); acc.w = fmaf(x, w.w, acc.w);
    }
    float d = g_dinv[u];
    acc.x *= d; acc.y *= d; acc.z *= d; acc.w *= d;
    ((float4*)g_xw)[(size_t)u * 16 + c4] = acc;
}

// ---------------- edge segment sum: dst[t,e,:] = binv * sum_{n in edge} xw[t,n,:]
template <int LAYER>
__global__ void k_eacc() {
    int slot = blockIdx.x * 4 + (threadIdx.x >> 6);
    int h = threadIdx.x & 63;
    if (slot >= TE) return;
    int t = slot / Ee;
    int beg = g_offE[slot], end = g_offE[slot + 1];
    const float* base = g_xw + (size_t)t * Nn * Hh + h;
    float acc = 0.f;
    for (int j = beg; j < end; j++) {
        int n = g_elist[j];
        acc += __ldg(base + (size_t)n * Hh);
    }
    float* dst = (LAYER == 0) ? g_edge1 : g_es;
    dst[(size_t)slot * Hh + h] = acc * g_binv[slot];
}

// ---------------- node segment sum: dst[t,n,:] = dinv * sum_{e of node} eacc[t,e,:]
template <int LAYER>
__global__ void k_nacc() {
    int slot = blockIdx.x * 4 + (threadIdx.x >> 6);
    int h = threadIdx.x & 63;
    if (slot >= TN) return;
    int t = slot / Nn;
    int beg = g_offN[slot], end = g_offN[slot + 1];
    const float* src = ((LAYER == 0) ? g_edge1 : g_es) + (size_t)t * Ee * Hh + h;
    float acc = 0.f;
    for (int j = beg; j < end; j++) {
        int e = g_nlist[j];
        acc += __ldg(src + (size_t)e * Hh);
    }
    float* dst = (LAYER == 0) ? g_h1 : g_xs;
    dst[(size_t)slot * Hh + h] = acc * g_dinv[slot];
}

// ---------------- per-node: aggregator conv + indiv_logit (channels 61..63 only)
__global__ void k_node(const float* __restrict__ nf,
                       const float* __restrict__ Wna, const float* __restrict__ bna,
                       const float* __restrict__ Wt,  const float* __restrict__ bt,
                       const float* __restrict__ Wr,  const float* __restrict__ br,
                       const float* __restrict__ Wf,  const float* __restrict__ bf,
                       float* __restrict__ out) {
    __shared__ float sh[Tt][Hh];
    __shared__ float shv[3][Tt];
    int n = blockIdx.x;
    int c = threadIdx.x;  // 64 threads
#pragma unroll
    for (int t = 0; t < Tt; t++) sh[t][c] = g_xs[((size_t)t * Nn + n) * Hh + c];
    __syncthreads();

    float acc[9];
#pragma unroll
    for (int s = 0; s < 9; s++) acc[s] = bna[c];
    const float* w = Wna + c * Hh * 3;
#pragma unroll 4
    for (int i = 0; i < Hh; i++) {
        float w0 = w[i * 3], w1 = w[i * 3 + 1], w2 = w[i * 3 + 2];
        float xv[11];
#pragma unroll
        for (int tau = 0; tau < 11; tau++) xv[tau] = sh[tau][i];
#pragma unroll
        for (int s = 0; s < 9; s++)
            acc[s] = fmaf(w0, xv[s], fmaf(w1, xv[s + 1], fmaf(w2, xv[s + 2], acc[s])));
    }
    size_t base = ((size_t)c * Nn + n) * 9;
#pragma unroll
    for (int s = 0; s < 9; s++) g_agg[base + s] = acc[s];

    if (c < 36) {
        int o3 = c / Tt, t = c % Tt;
        int o = 61 + o3;
        float xp = bt[o];
#pragma unroll
        for (int dk = 0; dk < 3; dk++) {
            int tau = t + dk - 1;
            if (tau >= 0 && tau < Tt) {
                const float* wt = Wt + o * Hh * 3 + dk;
#pragma unroll 8
                for (int i = 0; i < Hh; i++) xp = fmaf(wt[i * 3], sh[tau][i], xp);
            }
        }
        float rs = br[o];
        const float* xr = nf + ((size_t)t * Nn + n) * CINc;
#pragma unroll
        for (int cc = 0; cc < CINc; cc++) rs = fmaf(Wr[o * CINc + cc], xr[cc], rs);
        shv[o3][t] = fmaxf(xp + rs, 0.f);
    }
    __syncthreads();
    if (c < Pp) {
        float a = bf[c];
#pragma unroll
        for (int t = 0; t < Tt; t++)
#pragma unroll
            for (int dk = 0; dk < 3; dk++)
                a = fmaf(Wf[c * Tt * 3 + t * 3 + dk], shv[dk][t], a);
        out[(size_t)n * Pp + c] = a;
    }
}

// ---------------- per-edge aggregator conv ----------------
__global__ void k_eagg(const float* __restrict__ Wea, const float* __restrict__ bea) {
    __shared__ float sh[11][Hh];
    int e = blockIdx.x;
    int c = threadIdx.x;
#pragma unroll
    for (int t = 0; t < 11; t++) sh[t][c] = g_es[((size_t)t * Ee + e) * Hh + c];
    __syncthreads();
    float acc[9];
#pragma unroll
    for (int s = 0; s < 9; s++) acc[s] = bea[c];
    const float* w = Wea + c * Hh * 3;
#pragma unroll 4
    for (int i = 0; i < Hh; i++) {
        float w0 = w[i * 3], w1 = w[i * 3 + 1], w2 = w[i * 3 + 2];
        float xv[11];
#pragma unroll
        for (int tau = 0; tau < 11; tau++) xv[tau] = sh[tau][i];
#pragma unroll
        for (int s = 0; s < 9; s++)
            acc[s] = fmaf(w0, xv[s], fmaf(w1, xv[s + 1], fmaf(w2, xv[s + 2], acc[s])));
    }
    size_t base = ((size_t)c * Ee + e) * 9;
#pragma unroll
    for (int s = 0; s < 9; s++) g_eagg[base + s] = acc[s];
}

// ---------------- Wm1 transpose ----------------
__global__ void k_wm1t(const float* __restrict__ Wm1) {
    int i = blockIdx.x * blockDim.x + threadIdx.x;
    if (i >= 576 * Hh) return;
    g_wm1t[(i & 63) * 576 + (i >> 6)] = Wm1[i];
}

// ---------------- score MLP: 4 pairs per block, 64 threads (thread = hidden unit)
__global__ void k_mlp(const int* __restrict__ ni_full, const int* __restrict__ ei_full,
                      const int* __restrict__ nni, const int* __restrict__ nei,
                      const float* __restrict__ bm1, const float* __restrict__ Wm2,
                      const float* __restrict__ bm2, float* __restrict__ out) {
    __shared__ float4 z[4][144];
    __shared__ float red[4][2];
    int tid = threadIdx.x;
    int q0 = blockIdx.x * 4;
#pragma unroll
    for (int p = 0; p < 4; p++) {
        int q = q0 + p;
        int n, e;
        if (q < NNZn) { n = ni_full[11 * NNZn + q]; e = ei_full[11 * NNZn + q]; }
        else          { n = nni[q - NNZn];          e = nei[q - NNZn]; }
        const float4* ar = (const float4*)(g_agg + (size_t)n * 576);
        const float4* er = (const float4*)(g_eagg + (size_t)e * 576);
        for (int j = tid; j < 144; j += 64) {
            float4 a = ar[j], b = er[j];
            z[p][j] = make_float4(a.x * b.x, a.y * b.y, a.z * b.z, a.w * b.w);
        }
    }
    __syncthreads();
    int h = tid;
    float a0 = bm1[h], a1 = a0, a2 = a0, a3 = a0;
    const float4* wt = (const float4*)(g_wm1t + (size_t)h * 576);
#pragma unroll 4
    for (int j = 0; j < 144; j++) {
        float4 wv = wt[j];
        float4 z0 = z[0][j], z1 = z[1][j], z2 = z[2][j], z3 = z[3][j];
        a0 = fmaf(wv.x, z0.x, a0); a0 = fmaf(wv.y, z0.y, a0); a0 = fmaf(wv.z, z0.z, a0); a0 = fmaf(wv.w, z0.w, a0);
        a1 = fmaf(wv.x, z1.x, a1); a1 = fmaf(wv.y, z1.y, a1); a1 = fmaf(wv.z, z1.z, a1); a1 = fmaf(wv.w, z1.w, a1);
        a2 = fmaf(wv.x, z2.x, a2); a2 = fmaf(wv.y, z2.y, a2); a2 = fmaf(wv.z, z2.z, a2); a2 = fmaf(wv.w, z2.w, a2);
        a3 = fmaf(wv.x, z3.x, a3); a3 = fmaf(wv.y, z3.y, a3); a3 = fmaf(wv.z, z3.z, a3); a3 = fmaf(wv.w, z3.w, a3);
    }
    float wm2h = Wm2[h];
    float r0 = fmaxf(a0, 0.f) * wm2h;
    float r1 = fmaxf(a1, 0.f) * wm2h;
    float r2 = fmaxf(a2, 0.f) * wm2h;
    float r3 = fmaxf(a3, 0.f) * wm2h;
#pragma unroll
    for (int off = 16; off; off >>= 1) {
        r0 += __shfl_down_sync(0xffffffffu, r0, off);
        r1 += __shfl_down_sync(0xffffffffu, r1, off);
        r2 += __shfl_down_sync(0xffffffffu, r2, off);
        r3 += __shfl_down_sync(0xffffffffu, r3, off);
    }
    if ((tid & 31) == 0) {
        int wgi = tid >> 5;
        red[0][wgi] = r0; red[1][wgi] = r1; red[2][wgi] = r2; red[3][wgi] = r3;
    }
    __syncthreads();
    if (tid < 4) {
        float v = red[tid][0] + red[tid][1] + bm2[0];
        out[(size_t)Nn * Pp + q0 + tid] = v;
    }
}

// ---------------- host launcher (graph-capturable, allocation-free) ----------------
extern "C" void kernel_launch(void* const* d_in, const int* in_sizes, int n_in,
                              void* d_out, int out_size) {
    const float* nf  = (const float*)d_in[0];
    const float* W1  = (const float*)d_in[1];
    const float* b1  = (const float*)d_in[2];
    const float* W2  = (const float*)d_in[3];
    const float* b2  = (const float*)d_in[4];
    const float* Wt  = (const float*)d_in[5];
    const float* bt  = (const float*)d_in[6];
    const float* Wr  = (const float*)d_in[7];
    const float* br  = (const float*)d_in[8];
    const float* Wf  = (const float*)d_in[9];
    const float* bf  = (const float*)d_in[10];
    const float* Wna = (const float*)d_in[11];
    const float* bna = (const float*)d_in[12];
    const float* Wea = (const float*)d_in[13];
    const float* bea = (const float*)d_in[14];
    const float* Wm1 = (const float*)d_in[15];
    const float* bm1 = (const float*)d_in[16];
    const float* Wm2 = (const float*)d_in[17];
    const float* bm2 = (const float*)d_in[18];
    const int* node_idx = (const int*)d_in[19];
    const int* edge_idx = (const int*)d_in[20];
    const int* nni = (const int*)d_in[21];
    const int* nei = (const int*)d_in[22];
    float* out = (float*)d_out;

    // ---- CSR build ----
    k_zero<<<2048, 256>>>();
    k_count<<<(TNNZ + 255) / 256, 256>>>(node_idx, edge_idx);
    k_inv<<<(TN + 255) / 256, 256>>>();

    // exclusive scan of edge degrees -> g_offE  (SEL=0)
    {
        int nbE = (TE + 4095) / 4096;   // 59
        k_scanA<0><<<nbE, 256>>>();
        k_scanB<<<1, 1024>>>(nbE);
        k_scanC<0><<<nbE, 256>>>();
    }
    // exclusive scan of node degrees -> g_offN  (SEL=1)
    {
        int nbN = (TN + 4095) / 4096;   // 293
        k_scanA<1><<<nbN, 256>>>();
        k_scanB<<<1, 1024>>>(nbN);
        k_scanC<1><<<nbN, 256>>>();
    }
    k_fill<<<(TNNZ + 255) / 256, 256>>>(node_idx, edge_idx);

    // ---- layer 1 ----
    k_xw1<<<(TN + 15) / 16, 256>>>(nf, W1, b1);
    k_eacc<0><<<(TE + 3) / 4, 256>>>();
    k_nacc<0><<<(TN + 3) / 4, 256>>>();

    // ---- layer 2 ----
    k_xw2<<<(TN + 15) / 16, 256>>>(W2, b2);
    k_eacc<1><<<(TE + 3) / 4, 256>>>();
    k_nacc<1><<<(TN + 3) / 4, 256>>>();

    // ---- heads ----
    k_wm1t<<<(576 * Hh + 255) / 256, 256>>>(Wm1);
    k_node<<<Nn, 64>>>(nf, Wna, bna, Wt, bt, Wr, br, Wf, bf, out);
    k_eagg<<<Ee, 64>>>(Wea, bea);
    k_mlp<<<(2 * NNZn) / 4, 64>>>(node_idx, edge_idx, nni, nei, bm1, Wm2, bm2, out);
}

// round 5
// speedup vs baseline: 2.7624x; 2.6668x over previous
#include <cuda_runtime.h>

#define Tt   12
#define Nn   100000
#define CINc 16
#define Ee   20000
#define NNZn 160000
#define Hh   64
#define Pp   12

#define TN   (Tt * Nn)      // 1,200,000
#define TE   (Tt * Ee)      // 240,000
#define TNNZ (Tt * NNZn)    // 1,920,000

// ---------------- scratch (device globals) ----------------
__device__ float g_xs[(size_t)TN * Hh];
__device__ float g_h1[(size_t)TN * Hh];
__device__ float g_xw[(size_t)TN * Hh];
__device__ float g_es[(size_t)TE * Hh];
__device__ float g_edge1[(size_t)TE * Hh];
__device__ float g_agg[(size_t)Hh * Nn * 9];
__device__ float g_eagg[(size_t)Hh * Ee * 9];
__device__ float g_dinv[TN];
__device__ float g_binv[TE];
__device__ float g_wnat[192 * 64];   // Wna transposed [i3][c]
__device__ float g_weat[192 * 64];   // Wea transposed [i3][c]

// CSR scratch
__device__ int g_degN[TN];
__device__ int g_degE[TE];
__device__ int g_offN[TN + 1];
__device__ int g_offE[TE + 1];
__device__ int g_curN[TN];
__device__ int g_curE[TE];
__device__ int g_nlist[TNNZ];
__device__ int g_elist[TNNZ];
__device__ int g_part[1024];

// ---------------- zero (counts + cursors only) ----------------
__global__ void k_zero() {
    int i = blockIdx.x * blockDim.x + threadIdx.x;
    int stride = gridDim.x * blockDim.x;
    for (int j = i; j < TN; j += stride) { g_degN[j] = 0; g_curN[j] = 0; }
    for (int j = i; j < TE; j += stride) { g_degE[j] = 0; g_curE[j] = 0; }
}

__global__ void k_count(const int* __restrict__ ni, const int* __restrict__ ei) {
    int i = blockIdx.x * blockDim.x + threadIdx.x;
    if (i >= TNNZ) return;
    int t = i / NNZn;
    atomicAdd(&g_degN[t * Nn + ni[i]], 1);
    atomicAdd(&g_degE[t * Ee + ei[i]], 1);
}

__global__ void k_inv() {
    int i = blockIdx.x * blockDim.x + threadIdx.x;
    if (i < TN) { int d = g_degN[i]; g_dinv[i] = d > 0 ? rsqrtf((float)d) : 0.f; }
    if (i < TE) { int c = g_degE[i]; g_binv[i] = c > 0 ? 1.f / (float)c : 0.f; }
}

// ---------------- scan (SEL=0: edges, SEL=1: nodes) ----------------
template <int SEL>
__global__ void k_scanA() {
    const int* cnt = SEL ? g_degN : g_degE;
    const int n = SEL ? TN : TE;
    __shared__ int sh[256];
    int b = blockIdx.x, t = threadIdx.x;
    int i0 = b * 4096 + t * 16;
    int s = 0;
#pragma unroll
    for (int k = 0; k < 16; k++) { int i = i0 + k; if (i < n) s += cnt[i]; }
    sh[t] = s; __syncthreads();
    for (int off = 128; off; off >>= 1) {
        if (t < off) sh[t] += sh[t + off];
        __syncthreads();
    }
    if (t == 0) g_part[b] = sh[0];
}

__global__ void k_scanB(int nb) {
    __shared__ int sh[1024];
    int t = threadIdx.x;
    int v = (t < nb) ? g_part[t] : 0;
    sh[t] = v; __syncthreads();
    for (int off = 1; off < 1024; off <<= 1) {
        int a = (t >= off) ? sh[t - off] : 0;
        __syncthreads();
        sh[t] += a;
        __syncthreads();
    }
    if (t < nb) g_part[t] = sh[t] - v;
}

template <int SEL>
__global__ void k_scanC() {
    const int* cnt = SEL ? g_degN : g_degE;
    int* off = SEL ? g_offN : g_offE;
    const int n = SEL ? TN : TE;
    __shared__ int sh[256];
    int b = blockIdx.x, t = threadIdx.x;
    int i0 = b * 4096 + t * 16;
    int loc[16]; int s = 0;
#pragma unroll
    for (int k = 0; k < 16; k++) {
        int i = i0 + k;
        loc[k] = (i < n) ? cnt[i] : 0;
        s += loc[k];
    }
    sh[t] = s; __syncthreads();
    for (int o = 1; o < 256; o <<= 1) {
        int a = (t >= o) ? sh[t - o] : 0;
        __syncthreads();
        sh[t] += a;
        __syncthreads();
    }
    int run = g_part[b] + sh[t] - s;
#pragma unroll
    for (int k = 0; k < 16; k++) {
        int i = i0 + k;
        if (i < n) {
            off[i] = run;
            run += loc[k];
            if (i == n - 1) off[n] = run;
        }
    }
}

__global__ void k_fill(const int* __restrict__ ni, const int* __restrict__ ei) {
    int i = blockIdx.x * blockDim.x + threadIdx.x;
    if (i >= TNNZ) return;
    int t = i / NNZn;
    int n = ni[i], e = ei[i];
    int se = t * Ee + e, sn = t * Nn + n;
    int pe = atomicAdd(&g_curE[se], 1);
    g_elist[g_offE[se] + pe] = n;
    int pn = atomicAdd(&g_curN[sn], 1);
    g_nlist[g_offN[sn] + pn] = e;
}

// ---------------- weight transposes: Wna/Wea [c][i3] -> [i3][c] ----------------
__global__ void k_prep(const float* __restrict__ Wna, const float* __restrict__ Wea) {
    int i = blockIdx.x * blockDim.x + threadIdx.x;
    if (i >= 192 * 64) return;
    int c = i / 192, i3 = i % 192;
    g_wnat[i3 * 64 + c] = Wna[i];
    g_weat[i3 * 64 + c] = Wea[i];
}

// ---------------- xw1 = (x @ W1 + b1) * dinv ----------------
__global__ void k_xw1(const float* __restrict__ nf, const float* __restrict__ W1,
                      const float* __restrict__ b1) {
    __shared__ float4 sW[16 * 16];
    __shared__ float sb[64];
    int tid = threadIdx.x;
    sW[tid] = ((const float4*)W1)[tid];
    if (tid < 64) sb[tid] = b1[tid];
    __syncthreads();
    int u = blockIdx.x * 16 + (tid >> 4);
    int c4 = tid & 15;
    if (u >= TN) return;
    float d = g_dinv[u];
    const float4* x4 = (const float4*)(nf + (size_t)u * CINc);
    float xv[16];
#pragma unroll
    for (int q = 0; q < 4; q++) {
        float4 v = x4[q];
        xv[q * 4 + 0] = v.x; xv[q * 4 + 1] = v.y; xv[q * 4 + 2] = v.z; xv[q * 4 + 3] = v.w;
    }
    float4 acc = make_float4(sb[c4 * 4], sb[c4 * 4 + 1], sb[c4 * 4 + 2], sb[c4 * 4 + 3]);
#pragma unroll
    for (int c = 0; c < 16; c++) {
        float4 w = sW[c * 16 + c4];
        float x = xv[c];
        acc.x = fmaf(x, w.x, acc.x); acc.y = fmaf(x, w.y, acc.y);
        acc.z = fmaf(x, w.z, acc.z); acc.w = fmaf(x, w.w, acc.w);
    }
    acc.x *= d; acc.y *= d; acc.z *= d; acc.w *= d;
    ((float4*)g_xw)[(size_t)u * 16 + c4] = acc;
}

// ---------------- xw2 = (h1 @ W2 + b2) * dinv ----------------
__global__ void k_xw2(const float* __restrict__ W2, const float* __restrict__ b2) {
    __shared__ float4 sW[64 * 16];
    __shared__ float sX[16][65];
    __shared__ float sb[64];
    int tid = threadIdx.x;
    for (int j = tid; j < 64 * 16; j += 256) sW[j] = ((const float4*)W2)[j];
    if (tid < 64) sb[tid] = b2[tid];
    int u0 = blockIdx.x * 16;
    {
        int g = tid >> 4, k = tid & 15;
        int u = u0 + g;
        float4 v = (u < TN) ? ((const float4*)g_h1)[(size_t)u * 16 + k]
                            : make_float4(0.f, 0.f, 0.f, 0.f);
        sX[g][k * 4 + 0] = v.x; sX[g][k * 4 + 1] = v.y;
        sX[g][k * 4 + 2] = v.z; sX[g][k * 4 + 3] = v.w;
    }
    __syncthreads();
    int g = tid >> 4, c4 = tid & 15;
    int u = u0 + g;
    if (u >= TN) return;
    float4 acc = make_float4(sb[c4 * 4], sb[c4 * 4 + 1], sb[c4 * 4 + 2], sb[c4 * 4 + 3]);
#pragma unroll 8
    for (int c = 0; c < 64; c++) {
        float4 w = sW[c * 16 + c4];
        float x = sX[g][c];
        acc.x = fmaf(x, w.x, acc.x); acc.y = fmaf(x, w.y, acc.y);
        acc.z = fmaf(x, w.z, acc.z); acc.w = fmaf(x, w.w, acc.w);
    }
    float d = g_dinv[u];
    acc.x *= d; acc.y *= d; acc.z *= d; acc.w *= d;
    ((float4*)g_xw)[(size_t)u * 16 + c4] = acc;
}

// ---------------- edge segment sum ----------------
template <int LAYER>
__global__ void k_eacc() {
    int slot = blockIdx.x * 4 + (threadIdx.x >> 6);
    int h = threadIdx.x & 63;
    if (slot >= TE) return;
    int t = slot / Ee;
    int beg = g_offE[slot], end = g_offE[slot + 1];
    const float* base = g_xw + (size_t)t * Nn * Hh + h;
    float acc = 0.f;
    for (int j = beg; j < end; j++) {
        int n = g_elist[j];
        acc += __ldg(base + (size_t)n * Hh);
    }
    float* dst = (LAYER == 0) ? g_edge1 : g_es;
    dst[(size_t)slot * Hh + h] = acc * g_binv[slot];
}

// ---------------- node segment sum ----------------
template <int LAYER>
__global__ void k_nacc() {
    int slot = blockIdx.x * 4 + (threadIdx.x >> 6);
    int h = threadIdx.x & 63;
    if (slot >= TN) return;
    int t = slot / Nn;
    int beg = g_offN[slot], end = g_offN[slot + 1];
    const float* src = ((LAYER == 0) ? g_edge1 : g_es) + (size_t)t * Ee * Hh + h;
    float acc = 0.f;
    for (int j = beg; j < end; j++) {
        int e = g_nlist[j];
        acc += __ldg(src + (size_t)e * Hh);
    }
    float* dst = (LAYER == 0) ? g_h1 : g_xs;
    dst[(size_t)slot * Hh + h] = acc * g_dinv[slot];
}

// ---------------- per-node heads: 8 nodes/block, 512 threads ----------------
#define GN 8
#define CH 8   // i-chunk
__global__ void __launch_bounds__(512) k_node(
        const float* __restrict__ nf,
        const float* __restrict__ bna,
        const float* __restrict__ Wt,  const float* __restrict__ bt,
        const float* __restrict__ Wr,  const float* __restrict__ br,
        const float* __restrict__ Wf,  const float* __restrict__ bf,
        float* __restrict__ out) {
    __shared__ float sx[GN][64][16];       // [node][i][tau], 32 KB
    __shared__ float swc[CH * 3 * 64];     // weight chunk [ii3][c], 6 KB
    __shared__ float swt[3 * 192];         // Wt rows 61..63
    __shared__ float swr[3 * 16];          // Wr rows 61..63
    __shared__ float shv[GN][3][Tt];
    int tid = threadIdx.x;
    int g = tid >> 6, c = tid & 63;
    int n0 = blockIdx.x * GN;
    int n = n0 + g;

    // stage x: sx[g][c][t] = g_xs[(t*Nn + n)*64 + c]
#pragma unroll
    for (int t = 0; t < Tt; t++)
        sx[g][c][t] = g_xs[((size_t)t * Nn + n) * Hh + c];
    // stage temporal/residual weights (FIX: loop-stage full 576 with 512 threads)
    for (int j = tid; j < 576; j += 512)
        swt[j] = Wt[(61 + j / 192) * 192 + (j % 192)];
    if (tid < 48) swr[tid] = Wr[(61 + tid / 16) * 16 + (tid % 16)];

    float acc[9];
    float bn = bna[c];
#pragma unroll
    for (int s = 0; s < 9; s++) acc[s] = bn;

    for (int chunk = 0; chunk < 64 / CH; chunk++) {
        __syncthreads();
        // load weight chunk (contiguous, coalesced): 1536 floats
        for (int j = tid; j < CH * 3 * 64; j += 512)
            swc[j] = g_wnat[chunk * (CH * 3 * 64) + j];
        __syncthreads();
#pragma unroll
        for (int ii = 0; ii < CH; ii++) {
            int i = chunk * CH + ii;
            float4 x0 = *(const float4*)&sx[g][i][0];
            float4 x1 = *(const float4*)&sx[g][i][4];
            float4 x2 = *(const float4*)&sx[g][i][8];
            float xv[11] = {x0.x, x0.y, x0.z, x0.w, x1.x, x1.y, x1.z, x1.w,
                            x2.x, x2.y, x2.z};
            float w0 = swc[(ii * 3 + 0) * 64 + c];
            float w1 = swc[(ii * 3 + 1) * 64 + c];
            float w2 = swc[(ii * 3 + 2) * 64 + c];
#pragma unroll
            for (int s = 0; s < 9; s++)
                acc[s] = fmaf(w0, xv[s], fmaf(w1, xv[s + 1], fmaf(w2, xv[s + 2], acc[s])));
        }
    }
    {
        size_t base = ((size_t)c * Nn + n) * 9;
#pragma unroll
        for (int s = 0; s < 9; s++) g_agg[base + s] = acc[s];
    }

    // temporal conv + residual + relu (channels 61..63 only)
    if (c < 36) {
        int o3 = c / Tt, t = c % Tt;
        float xp = bt[61 + o3];
#pragma unroll
        for (int dk = 0; dk < 3; dk++) {
            int tau = t + dk - 1;
            if (tau >= 0 && tau < Tt) {
                const float* wt = swt + o3 * 192 + dk;
#pragma unroll 8
                for (int i = 0; i < 64; i++) xp = fmaf(wt[i * 3], sx[g][i][tau], xp);
            }
        }
        float rs = br[61 + o3];
        const float* xr = nf + ((size_t)t * Nn + n) * CINc;
#pragma unroll
        for (int cc = 0; cc < CINc; cc++) rs = fmaf(swr[o3 * 16 + cc], xr[cc], rs);
        shv[g][o3][t] = fmaxf(xp + rs, 0.f);
    }
    __syncthreads();
    if (c < Pp) {
        float a = bf[c];
#pragma unroll
        for (int t = 0; t < Tt; t++)
#pragma unroll
            for (int dk = 0; dk < 3; dk++)
                a = fmaf(Wf[c * 36 + t * 3 + dk], shv[g][dk][t], a);
        out[(size_t)n * Pp + c] = a;
    }
}

// ---------------- per-edge aggregator: 8 edges/block ----------------
__global__ void __launch_bounds__(512) k_eagg(const float* __restrict__ bea) {
    __shared__ float sx[GN][64][16];
    __shared__ float swc[CH * 3 * 64];
    int tid = threadIdx.x;
    int g = tid >> 6, c = tid & 63;
    int e = blockIdx.x * GN + g;

#pragma unroll
    for (int t = 0; t < 11; t++)
        sx[g][c][t] = g_es[((size_t)t * Ee + e) * Hh + c];
    sx[g][c][11] = 0.f;   // keep float4 read of [8..11] deterministic

    float acc[9];
    float bn = bea[c];
#pragma unroll
    for (int s = 0; s < 9; s++) acc[s] = bn;

    for (int chunk = 0; chunk < 64 / CH; chunk++) {
        __syncthreads();
        for (int j = tid; j < CH * 3 * 64; j += 512)
            swc[j] = g_weat[chunk * (CH * 3 * 64) + j];
        __syncthreads();
#pragma unroll
        for (int ii = 0; ii < CH; ii++) {
            int i = chunk * CH + ii;
            float4 x0 = *(const float4*)&sx[g][i][0];
            float4 x1 = *(const float4*)&sx[g][i][4];
            float4 x2 = *(const float4*)&sx[g][i][8];
            float xv[11] = {x0.x, x0.y, x0.z, x0.w, x1.x, x1.y, x1.z, x1.w,
                            x2.x, x2.y, x2.z};
            float w0 = swc[(ii * 3 + 0) * 64 + c];
            float w1 = swc[(ii * 3 + 1) * 64 + c];
            float w2 = swc[(ii * 3 + 2) * 64 + c];
#pragma unroll
            for (int s = 0; s < 9; s++)
                acc[s] = fmaf(w0, xv[s], fmaf(w1, xv[s + 1], fmaf(w2, xv[s + 2], acc[s])));
        }
    }
    size_t base = ((size_t)c * Ee + e) * 9;
#pragma unroll
    for (int s = 0; s < 9; s++) g_eagg[base + s] = acc[s];
}

// ---------------- score MLP: tiled GEMM, 64 pairs x 64 h per block ----------------
__global__ void __launch_bounds__(256) k_mlp(
        const int* __restrict__ ni_full, const int* __restrict__ ei_full,
        const int* __restrict__ nni, const int* __restrict__ nei,
        const float* __restrict__ Wm1, const float* __restrict__ bm1,
        const float* __restrict__ Wm2, const float* __restrict__ bm2,
        float* __restrict__ out) {
    __shared__ float zs[64][64];     // [k_local][pair]
    __shared__ float ws[64][64];     // [k_local][h]
    __shared__ float red[64][17];
    __shared__ int sn[64], se[64];
    int tid = threadIdx.x;
    int q0 = blockIdx.x * 64;
    if (tid < 64) {
        int q = q0 + tid;
        int n, e;
        if (q < NNZn) { n = ni_full[11 * NNZn + q]; e = ei_full[11 * NNZn + q]; }
        else          { n = nni[q - NNZn];          e = nei[q - NNZn]; }
        sn[tid] = n; se[tid] = e;
    }
    __syncthreads();

    int r = tid >> 4, cg = tid & 15;   // r: pair group (4 pairs), cg: h group (4 h)
    float acc[4][4];
#pragma unroll
    for (int i = 0; i < 4; i++)
#pragma unroll
        for (int j = 0; j < 4; j++) acc[i][j] = 0.f;

    int p = tid >> 2, kq = tid & 3;    // staging roles
    const float4* ag4 = (const float4*)g_agg;
    const float4* eg4 = (const float4*)g_eagg;
    const float4* wm4 = (const float4*)Wm1;
    int an = sn[p] * 144, ae = se[p] * 144;

    for (int chunk = 0; chunk < 9; chunk++) {
        __syncthreads();
        // stage weights: 64k x 64h = 1024 float4, contiguous
        for (int j = tid; j < 1024; j += 256)
            *((float4*)&ws[0][0] + j) = wm4[chunk * 1024 + j];
        // stage z = a .* e for 64 pairs x 64 k
#pragma unroll
        for (int jj = 0; jj < 4; jj++) {
            int off = kq * 4 + jj;                 // float4 index within chunk
            float4 a = ag4[an + chunk * 16 + off];
            float4 b = eg4[ae + chunk * 16 + off];
            int k = off * 4;
            zs[k + 0][p] = a.x * b.x;
            zs[k + 1][p] = a.y * b.y;
            zs[k + 2][p] = a.z * b.z;
            zs[k + 3][p] = a.w * b.w;
        }
        __syncthreads();
#pragma unroll 4
        for (int kl = 0; kl < 64; kl++) {
            float4 zv = *(const float4*)&zs[kl][r * 4];
            float4 wv = *(const float4*)&ws[kl][cg * 4];
            acc[0][0] = fmaf(zv.x, wv.x, acc[0][0]); acc[0][1] = fmaf(zv.x, wv.y, acc[0][1]);
            acc[0][2] = fmaf(zv.x, wv.z, acc[0][2]); acc[0][3] = fmaf(zv.x, wv.w, acc[0][3]);
            acc[1][0] = fmaf(zv.y, wv.x, acc[1][0]); acc[1][1] = fmaf(zv.y, wv.y, acc[1][1]);
            acc[1][2] = fmaf(zv.y, wv.z, acc[1][2]); acc[1][3] = fmaf(zv.y, wv.w, acc[1][3]);
            acc[2][0] = fmaf(zv.z, wv.x, acc[2][0]); acc[2][1] = fmaf(zv.z, wv.y, acc[2][1]);
            acc[2][2] = fmaf(zv.z, wv.z, acc[2][2]); acc[2][3] = fmaf(zv.z, wv.w, acc[2][3]);
            acc[3][0] = fmaf(zv.w, wv.x, acc[3][0]); acc[3][1] = fmaf(zv.w, wv.y, acc[3][1]);
            acc[3][2] = fmaf(zv.w, wv.z, acc[3][2]); acc[3][3] = fmaf(zv.w, wv.w, acc[3][3]);
        }
    }

    // epilogue: relu(acc + bm1) @ Wm2, reduce over h
    float b0 = bm1[cg * 4 + 0], b1 = bm1[cg * 4 + 1];
    float b2 = bm1[cg * 4 + 2], b3 = bm1[cg * 4 + 3];
    float w0 = Wm2[cg * 4 + 0], w1 = Wm2[cg * 4 + 1];
    float w2 = Wm2[cg * 4 + 2], w3 = Wm2[cg * 4 + 3];
#pragma unroll
    for (int pi = 0; pi < 4; pi++) {
        float part = fmaxf(acc[pi][0] + b0, 0.f) * w0
                   + fmaxf(acc[pi][1] + b1, 0.f) * w1
                   + fmaxf(acc[pi][2] + b2, 0.f) * w2
                   + fmaxf(acc[pi][3] + b3, 0.f) * w3;
        red[r * 4 + pi][cg] = part;
    }
    __syncthreads();
    if (tid < 64) {
        float v = bm2[0];
#pragma unroll
        for (int j = 0; j < 16; j++) v += red[tid][j];
        out[(size_t)Nn * Pp + q0 + tid] = v;
    }
}

// ---------------- host launcher ----------------
extern "C" void kernel_launch(void* const* d_in, const int* in_sizes, int n_in,
                              void* d_out, int out_size) {
    const float* nf  = (const float*)d_in[0];
    const float* W1  = (const float*)d_in[1];
    const float* b1  = (const float*)d_in[2];
    const float* W2  = (const float*)d_in[3];
    const float* b2  = (const float*)d_in[4];
    const float* Wt  = (const float*)d_in[5];
    const float* bt  = (const float*)d_in[6];
    const float* Wr  = (const float*)d_in[7];
    const float* br  = (const float*)d_in[8];
    const float* Wf  = (const float*)d_in[9];
    const float* bf  = (const float*)d_in[10];
    const float* Wna = (const float*)d_in[11];
    const float* bna = (const float*)d_in[12];
    const float* Wea = (const float*)d_in[13];
    const float* bea = (const float*)d_in[14];
    const float* Wm1 = (const float*)d_in[15];
    const float* bm1 = (const float*)d_in[16];
    const float* Wm2 = (const float*)d_in[17];
    const float* bm2 = (const float*)d_in[18];
    const int* node_idx = (const int*)d_in[19];
    const int* edge_idx = (const int*)d_in[20];
    const int* nni = (const int*)d_in[21];
    const int* nei = (const int*)d_in[22];
    float* out = (float*)d_out;

    // ---- CSR build ----
    k_zero<<<2048, 256>>>();
    k_count<<<(TNNZ + 255) / 256, 256>>>(node_idx, edge_idx);
    k_inv<<<(TN + 255) / 256, 256>>>();
    {
        int nbE = (TE + 4095) / 4096;
        k_scanA<0><<<nbE, 256>>>();
        k_scanB<<<1, 1024>>>(nbE);
        k_scanC<0><<<nbE, 256>>>();
    }
    {
        int nbN = (TN + 4095) / 4096;
        k_scanA<1><<<nbN, 256>>>();
        k_scanB<<<1, 1024>>>(nbN);
        k_scanC<1><<<nbN, 256>>>();
    }
    k_fill<<<(TNNZ + 255) / 256, 256>>>(node_idx, edge_idx);
    k_prep<<<(192 * 64 + 255) / 256, 256>>>(Wna, Wea);

    // ---- layer 1 ----
    k_xw1<<<(TN + 15) / 16, 256>>>(nf, W1, b1);
    k_eacc<0><<<(TE + 3) / 4, 256>>>();
    k_nacc<0><<<(TN + 3) / 4, 256>>>();

    // ---- layer 2 ----
    k_xw2<<<(TN + 15) / 16, 256>>>(W2, b2);
    k_eacc<1><<<(TE + 3) / 4, 256>>>();
    k_nacc<1><<<(TN + 3) / 4, 256>>>();

    // ---- heads ----
    k_node<<<Nn / GN, 512>>>(nf, bna, Wt, bt, Wr, br, Wf, bf, out);
    k_eagg<<<Ee / GN, 512>>>(bea);
    k_mlp<<<(2 * NNZn) / 64, 256>>>(node_idx, edge_idx, nni, nei, Wm1, bm1, Wm2, bm2, out);
}

// round 6
// speedup vs baseline: 2.8847x; 1.0443x over previous
#include <cuda_runtime.h>

#define Tt   12
#define Nn   100000
#define CINc 16
#define Ee   20000
#define NNZn 160000
#define Hh   64
#define Pp   12

#define TN   (Tt * Nn)
#define TE   (Tt * Ee)
#define TNNZ (Tt * NNZn)

typedef unsigned long long u64;

// ---- f32x2 packed helpers (Blackwell) ----
__device__ __forceinline__ u64 pk2(float lo, float hi) {
    u64 r;
    asm("mov.b64 %0, {%1, %2};" : "=l"(r) : "f"(lo), "f"(hi));
    return r;
}
__device__ __forceinline__ void upk2(float& lo, float& hi, u64 v) {
    asm("mov.b64 {%0, %1}, %2;" : "=f"(lo), "=f"(hi) : "l"(v));
}
__device__ __forceinline__ u64 fma2(u64 a, u64 b, u64 c) {
    u64 d;
    asm("fma.rn.f32x2 %0, %1, %2, %3;" : "=l"(d) : "l"(a), "l"(b), "l"(c));
    return d;
}

// ---------------- scratch ----------------
__device__ float g_xs[(size_t)TN * Hh];
__device__ float g_h1[(size_t)TN * Hh];
__device__ float g_xw[(size_t)TN * Hh];
__device__ float g_es[(size_t)TE * Hh];
__device__ float g_edge1[(size_t)TE * Hh];
__device__ float g_agg[(size_t)Hh * Nn * 9];
__device__ float g_eagg[(size_t)Hh * Ee * 9];
__device__ float g_dinv[TN];
__device__ float g_binv[TE];
__device__ float g_wnat2[192 * 64];   // Wna packed pairs: [(i3)*32+cp] -> {W[cp][i3], W[cp+32][i3]}
__device__ float g_weat2[192 * 64];   // Wea same

__device__ int g_degN[TN];
__device__ int g_degE[TE];
__device__ int g_offN[TN + 1];
__device__ int g_offE[TE + 1];
__device__ int g_curN[TN];
__device__ int g_curE[TE];
__device__ int g_nlist[TNNZ];
__device__ int g_elist[TNNZ];
__device__ int g_part[1024];

// ---------------- zero ----------------
__global__ void k_zero() {
    int i = blockIdx.x * blockDim.x + threadIdx.x;
    int stride = gridDim.x * blockDim.x;
    for (int j = i; j < TN; j += stride) { g_degN[j] = 0; g_curN[j] = 0; }
    for (int j = i; j < TE; j += stride) { g_degE[j] = 0; g_curE[j] = 0; }
}

__global__ void k_count(const int* __restrict__ ni, const int* __restrict__ ei) {
    int i = blockIdx.x * blockDim.x + threadIdx.x;
    if (i >= TNNZ) return;
    int t = i / NNZn;
    atomicAdd(&g_degN[t * Nn + ni[i]], 1);
    atomicAdd(&g_degE[t * Ee + ei[i]], 1);
}

__global__ void k_inv() {
    int i = blockIdx.x * blockDim.x + threadIdx.x;
    if (i < TN) { int d = g_degN[i]; g_dinv[i] = d > 0 ? rsqrtf((float)d) : 0.f; }
    if (i < TE) { int c = g_degE[i]; g_binv[i] = c > 0 ? 1.f / (float)c : 0.f; }
}

// ---------------- scans ----------------
template <int SEL>
__global__ void k_scanA() {
    const int* cnt = SEL ? g_degN : g_degE;
    const int n = SEL ? TN : TE;
    __shared__ int sh[256];
    int b = blockIdx.x, t = threadIdx.x;
    int i0 = b * 4096 + t * 16;
    int s = 0;
#pragma unroll
    for (int k = 0; k < 16; k++) { int i = i0 + k; if (i < n) s += cnt[i]; }
    sh[t] = s; __syncthreads();
    for (int off = 128; off; off >>= 1) {
        if (t < off) sh[t] += sh[t + off];
        __syncthreads();
    }
    if (t == 0) g_part[b] = sh[0];
}

__global__ void k_scanB(int nb) {
    __shared__ int sh[1024];
    int t = threadIdx.x;
    int v = (t < nb) ? g_part[t] : 0;
    sh[t] = v; __syncthreads();
    for (int off = 1; off < 1024; off <<= 1) {
        int a = (t >= off) ? sh[t - off] : 0;
        __syncthreads();
        sh[t] += a;
        __syncthreads();
    }
    if (t < nb) g_part[t] = sh[t] - v;
}

template <int SEL>
__global__ void k_scanC() {
    const int* cnt = SEL ? g_degN : g_degE;
    int* off = SEL ? g_offN : g_offE;
    const int n = SEL ? TN : TE;
    __shared__ int sh[256];
    int b = blockIdx.x, t = threadIdx.x;
    int i0 = b * 4096 + t * 16;
    int loc[16]; int s = 0;
#pragma unroll
    for (int k = 0; k < 16; k++) {
        int i = i0 + k;
        loc[k] = (i < n) ? cnt[i] : 0;
        s += loc[k];
    }
    sh[t] = s; __syncthreads();
    for (int o = 1; o < 256; o <<= 1) {
        int a = (t >= o) ? sh[t - o] : 0;
        __syncthreads();
        sh[t] += a;
        __syncthreads();
    }
    int run = g_part[b] + sh[t] - s;
#pragma unroll
    for (int k = 0; k < 16; k++) {
        int i = i0 + k;
        if (i < n) {
            off[i] = run;
            run += loc[k];
            if (i == n - 1) off[n] = run;
        }
    }
}

__global__ void k_fill(const int* __restrict__ ni, const int* __restrict__ ei) {
    int i = blockIdx.x * blockDim.x + threadIdx.x;
    if (i >= TNNZ) return;
    int t = i / NNZn;
    int n = ni[i], e = ei[i];
    int se = t * Ee + e, sn = t * Nn + n;
    int pe = atomicAdd(&g_curE[se], 1);
    g_elist[g_offE[se] + pe] = n;
    int pn = atomicAdd(&g_curN[sn], 1);
    g_nlist[g_offN[sn] + pn] = e;
}

// ---------------- weight prep: packed channel-pair transposes ----------------
__global__ void k_prep(const float* __restrict__ Wna, const float* __restrict__ Wea) {
    int i = blockIdx.x * blockDim.x + threadIdx.x;
    if (i >= 192 * 64) return;
    int c = i / 192, i3 = i % 192;
    int cp = c & 31, hi = c >> 5;
    g_wnat2[(i3 * 32 + cp) * 2 + hi] = Wna[i];
    g_weat2[(i3 * 32 + cp) * 2 + hi] = Wea[i];
}

// ---------------- xw1 = (x @ W1 + b1) * dinv ----------------
__global__ void k_xw1(const float* __restrict__ nf, const float* __restrict__ W1,
                      const float* __restrict__ b1) {
    __shared__ float4 sW[16 * 16];
    __shared__ float sb[64];
    int tid = threadIdx.x;
    sW[tid] = ((const float4*)W1)[tid];
    if (tid < 64) sb[tid] = b1[tid];
    __syncthreads();
    int u = blockIdx.x * 16 + (tid >> 4);
    int c4 = tid & 15;
    if (u >= TN) return;
    float d = g_dinv[u];
    const float4* x4 = (const float4*)(nf + (size_t)u * CINc);
    float xv[16];
#pragma unroll
    for (int q = 0; q < 4; q++) {
        float4 v = x4[q];
        xv[q * 4 + 0] = v.x; xv[q * 4 + 1] = v.y; xv[q * 4 + 2] = v.z; xv[q * 4 + 3] = v.w;
    }
    u64 acc01 = pk2(sb[c4 * 4 + 0], sb[c4 * 4 + 1]);
    u64 acc23 = pk2(sb[c4 * 4 + 2], sb[c4 * 4 + 3]);
#pragma unroll
    for (int c = 0; c < 16; c++) {
        ulonglong2 w = *(const ulonglong2*)&sW[c * 16 + c4];
        u64 x2 = pk2(xv[c], xv[c]);
        acc01 = fma2(x2, w.x, acc01);
        acc23 = fma2(x2, w.y, acc23);
    }
    float4 r;
    upk2(r.x, r.y, acc01);
    upk2(r.z, r.w, acc23);
    r.x *= d; r.y *= d; r.z *= d; r.w *= d;
    ((float4*)g_xw)[(size_t)u * 16 + c4] = r;
}

// ---------------- xw2 = (h1 @ W2 + b2) * dinv ----------------
__global__ void k_xw2(const float* __restrict__ W2, const float* __restrict__ b2) {
    __shared__ float4 sW[64 * 16];
    __shared__ float sX[16][65];
    __shared__ float sb[64];
    int tid = threadIdx.x;
    for (int j = tid; j < 64 * 16; j += 256) sW[j] = ((const float4*)W2)[j];
    if (tid < 64) sb[tid] = b2[tid];
    int u0 = blockIdx.x * 16;
    {
        int g = tid >> 4, k = tid & 15;
        int u = u0 + g;
        float4 v = (u < TN) ? ((const float4*)g_h1)[(size_t)u * 16 + k]
                            : make_float4(0.f, 0.f, 0.f, 0.f);
        sX[g][k * 4 + 0] = v.x; sX[g][k * 4 + 1] = v.y;
        sX[g][k * 4 + 2] = v.z; sX[g][k * 4 + 3] = v.w;
    }
    __syncthreads();
    int g = tid >> 4, c4 = tid & 15;
    int u = u0 + g;
    if (u >= TN) return;
    u64 acc01 = pk2(sb[c4 * 4 + 0], sb[c4 * 4 + 1]);
    u64 acc23 = pk2(sb[c4 * 4 + 2], sb[c4 * 4 + 3]);
#pragma unroll 8
    for (int c = 0; c < 64; c++) {
        ulonglong2 w = *(const ulonglong2*)&sW[c * 16 + c4];
        float x = sX[g][c];
        u64 x2 = pk2(x, x);
        acc01 = fma2(x2, w.x, acc01);
        acc23 = fma2(x2, w.y, acc23);
    }
    float d = g_dinv[u];
    float4 r;
    upk2(r.x, r.y, acc01);
    upk2(r.z, r.w, acc23);
    r.x *= d; r.y *= d; r.z *= d; r.w *= d;
    ((float4*)g_xw)[(size_t)u * 16 + c4] = r;
}

// ---------------- edge segment sum ----------------
template <int LAYER>
__global__ void k_eacc() {
    int slot = blockIdx.x * 4 + (threadIdx.x >> 6);
    int h = threadIdx.x & 63;
    if (slot >= TE) return;
    int t = slot / Ee;
    int beg = g_offE[slot], end = g_offE[slot + 1];
    const float* base = g_xw + (size_t)t * Nn * Hh + h;
    float acc = 0.f;
    for (int j = beg; j < end; j++) {
        int n = g_elist[j];
        acc += __ldg(base + (size_t)n * Hh);
    }
    float* dst = (LAYER == 0) ? g_edge1 : g_es;
    dst[(size_t)slot * Hh + h] = acc * g_binv[slot];
}

// ---------------- node segment sum ----------------
template <int LAYER>
__global__ void k_nacc() {
    int slot = blockIdx.x * 4 + (threadIdx.x >> 6);
    int h = threadIdx.x & 63;
    if (slot >= TN) return;
    int t = slot / Nn;
    int beg = g_offN[slot], end = g_offN[slot + 1];
    const float* src = ((LAYER == 0) ? g_edge1 : g_es) + (size_t)t * Ee * Hh + h;
    float acc = 0.f;
    for (int j = beg; j < end; j++) {
        int e = g_nlist[j];
        acc += __ldg(src + (size_t)e * Hh);
    }
    float* dst = (LAYER == 0) ? g_h1 : g_xs;
    dst[(size_t)slot * Hh + h] = acc * g_dinv[slot];
}

// ---------------- per-node heads: 8 nodes x 32 c-pairs = 256 threads ----------------
#define GN 8
#define CH 8
__global__ void __launch_bounds__(256) k_node(
        const float* __restrict__ nf,
        const float* __restrict__ bna,
        const float* __restrict__ Wt,  const float* __restrict__ bt,
        const float* __restrict__ Wr,  const float* __restrict__ br,
        const float* __restrict__ Wf,  const float* __restrict__ bf,
        float* __restrict__ out) {
    __shared__ float sx[GN][64][12];      // [node][i][tau], 24 KB
    __shared__ u64 swc2[CH * 3 * 32];     // packed weight chunk [ii3][cp], 6 KB
    __shared__ float swt[3 * 192];
    __shared__ float swr[3 * 16];
    __shared__ float shv[GN][3][Tt];
    int tid = threadIdx.x;
    int g = tid >> 5, cp = tid & 31;
    int n = blockIdx.x * GN + g;

    // stage x (both channel halves)
#pragma unroll
    for (int t = 0; t < Tt; t++) {
        sx[g][cp][t]      = g_xs[((size_t)t * Nn + n) * Hh + cp];
        sx[g][cp + 32][t] = g_xs[((size_t)t * Nn + n) * Hh + cp + 32];
    }
    for (int j = tid; j < 576; j += 256)
        swt[j] = Wt[(61 + j / 192) * 192 + (j % 192)];
    if (tid < 48) swr[tid] = Wr[(61 + tid / 16) * 16 + (tid % 16)];

    u64 acc2[9];
    {
        u64 b2 = pk2(bna[cp], bna[cp + 32]);
#pragma unroll
        for (int s = 0; s < 9; s++) acc2[s] = b2;
    }

    const u64* gw2 = (const u64*)g_wnat2;
    for (int chunk = 0; chunk < 64 / CH; chunk++) {
        __syncthreads();
        for (int j = tid; j < CH * 3 * 32; j += 256)
            swc2[j] = gw2[chunk * (CH * 3 * 32) + j];
        __syncthreads();
#pragma unroll
        for (int ii = 0; ii < CH; ii++) {
            int i = chunk * CH + ii;
            float4 x0 = *(const float4*)&sx[g][i][0];
            float4 x1 = *(const float4*)&sx[g][i][4];
            float4 x2 = *(const float4*)&sx[g][i][8];
            float xv[11] = {x0.x, x0.y, x0.z, x0.w, x1.x, x1.y, x1.z, x1.w,
                            x2.x, x2.y, x2.z};
            u64 xd[11];
#pragma unroll
            for (int s = 0; s < 11; s++) xd[s] = pk2(xv[s], xv[s]);
            u64 w0 = swc2[(ii * 3 + 0) * 32 + cp];
            u64 w1 = swc2[(ii * 3 + 1) * 32 + cp];
            u64 w2 = swc2[(ii * 3 + 2) * 32 + cp];
#pragma unroll
            for (int s = 0; s < 9; s++) {
                acc2[s] = fma2(w0, xd[s], acc2[s]);
                acc2[s] = fma2(w1, xd[s + 1], acc2[s]);
                acc2[s] = fma2(w2, xd[s + 2], acc2[s]);
            }
        }
    }
    {
        size_t b0 = ((size_t)cp * Nn + n) * 9;
        size_t b1 = ((size_t)(cp + 32) * Nn + n) * 9;
#pragma unroll
        for (int s = 0; s < 9; s++) {
            float lo, hi;
            upk2(lo, hi, acc2[s]);
            g_agg[b0 + s] = lo;
            g_agg[b1 + s] = hi;
        }
    }

    // indiv logit: 8 nodes x 3 o x 12 t = 288 units
    for (int u = tid; u < GN * 36; u += 256) {
        int gg = u / 36, r = u % 36;
        int o3 = r / Tt, t = r % Tt;
        int nn = blockIdx.x * GN + gg;
        float xp = bt[61 + o3];
#pragma unroll
        for (int dk = 0; dk < 3; dk++) {
            int tau = t + dk - 1;
            if (tau >= 0 && tau < Tt) {
                const float* wt = swt + o3 * 192 + dk;
#pragma unroll 8
                for (int i = 0; i < 64; i++) xp = fmaf(wt[i * 3], sx[gg][i][tau], xp);
            }
        }
        float rs = br[61 + o3];
        const float* xr = nf + ((size_t)t * Nn + nn) * CINc;
#pragma unroll
        for (int cc = 0; cc < CINc; cc++) rs = fmaf(swr[o3 * 16 + cc], xr[cc], rs);
        shv[gg][o3][t] = fmaxf(xp + rs, 0.f);
    }
    __syncthreads();
    if (tid < GN * Pp) {
        int gg = tid / Pp, pc = tid % Pp;
        int nn = blockIdx.x * GN + gg;
        float a = bf[pc];
#pragma unroll
        for (int t = 0; t < Tt; t++)
#pragma unroll
            for (int dk = 0; dk < 3; dk++)
                a = fmaf(Wf[pc * 36 + t * 3 + dk], shv[gg][dk][t], a);
        out[(size_t)nn * Pp + pc] = a;
    }
}

// ---------------- per-edge aggregator ----------------
__global__ void __launch_bounds__(256) k_eagg(const float* __restrict__ bea) {
    __shared__ float sx[GN][64][12];
    __shared__ u64 swc2[CH * 3 * 32];
    int tid = threadIdx.x;
    int g = tid >> 5, cp = tid & 31;
    int e = blockIdx.x * GN + g;

#pragma unroll
    for (int t = 0; t < 11; t++) {
        sx[g][cp][t]      = g_es[((size_t)t * Ee + e) * Hh + cp];
        sx[g][cp + 32][t] = g_es[((size_t)t * Ee + e) * Hh + cp + 32];
    }
    sx[g][cp][11] = 0.f;
    sx[g][cp + 32][11] = 0.f;

    u64 acc2[9];
    {
        u64 b2 = pk2(bea[cp], bea[cp + 32]);
#pragma unroll
        for (int s = 0; s < 9; s++) acc2[s] = b2;
    }

    const u64* gw2 = (const u64*)g_weat2;
    for (int chunk = 0; chunk < 64 / CH; chunk++) {
        __syncthreads();
        for (int j = tid; j < CH * 3 * 32; j += 256)
            swc2[j] = gw2[chunk * (CH * 3 * 32) + j];
        __syncthreads();
#pragma unroll
        for (int ii = 0; ii < CH; ii++) {
            int i = chunk * CH + ii;
            float4 x0 = *(const float4*)&sx[g][i][0];
            float4 x1 = *(const float4*)&sx[g][i][4];
            float4 x2 = *(const float4*)&sx[g][i][8];
            float xv[11] = {x0.x, x0.y, x0.z, x0.w, x1.x, x1.y, x1.z, x1.w,
                            x2.x, x2.y, x2.z};
            u64 xd[11];
#pragma unroll
            for (int s = 0; s < 11; s++) xd[s] = pk2(xv[s], xv[s]);
            u64 w0 = swc2[(ii * 3 + 0) * 32 + cp];
            u64 w1 = swc2[(ii * 3 + 1) * 32 + cp];
            u64 w2 = swc2[(ii * 3 + 2) * 32 + cp];
#pragma unroll
            for (int s = 0; s < 9; s++) {
                acc2[s] = fma2(w0, xd[s], acc2[s]);
                acc2[s] = fma2(w1, xd[s + 1], acc2[s]);
                acc2[s] = fma2(w2, xd[s + 2], acc2[s]);
            }
        }
    }
    size_t b0 = ((size_t)cp * Ee + e) * 9;
    size_t b1 = ((size_t)(cp + 32) * Ee + e) * 9;
#pragma unroll
    for (int s = 0; s < 9; s++) {
        float lo, hi;
        upk2(lo, hi, acc2[s]);
        g_eagg[b0 + s] = lo;
        g_eagg[b1 + s] = hi;
    }
}

// ---------------- score MLP: 128 pairs x 64 h, 128 threads, 8p x 8h tiles ----------------
__global__ void __launch_bounds__(128) k_mlp(
        const int* __restrict__ ni_full, const int* __restrict__ ei_full,
        const int* __restrict__ nni, const int* __restrict__ nei,
        const float* __restrict__ Wm1, const float* __restrict__ bm1,
        const float* __restrict__ Wm2, const float* __restrict__ bm2,
        float* __restrict__ out) {
    __shared__ float zs[32][128];    // [k_local][pair] 16 KB
    __shared__ float ws[32][64];     // [k_local][h]    8 KB
    __shared__ float red[128][9];
    __shared__ int sn[128], se[128];
    int tid = threadIdx.x;
    int q0 = blockIdx.x * 128;
    {
        int q = q0 + tid;
        int n, e;
        if (q < NNZn) { n = ni_full[11 * NNZn + q]; e = ei_full[11 * NNZn + q]; }
        else          { n = nni[q - NNZn];          e = nei[q - NNZn]; }
        sn[tid] = n; se[tid] = e;
    }
    __syncthreads();

    int tp = tid >> 3, th = tid & 7;   // pair-group (8p each), h-group (8h each)
    u64 acc2[4][8];                    // [p-pair][h]
#pragma unroll
    for (int i = 0; i < 4; i++)
#pragma unroll
        for (int j = 0; j < 8; j++) acc2[i][j] = 0;

    const float4* ag4 = (const float4*)g_agg;
    const float4* eg4 = (const float4*)g_eagg;
    const float4* wm4 = (const float4*)Wm1;
    int an = sn[tid] * 144, ae = se[tid] * 144;

    for (int chunk = 0; chunk < 18; chunk++) {
        __syncthreads();
        // stage weights: 32k x 64h = 512 float4
        for (int j = tid; j < 512; j += 128)
            *((float4*)&ws[0][0] + j) = wm4[chunk * 512 + j];
        // stage z for own pair: 32 k values
#pragma unroll
        for (int j = 0; j < 8; j++) {
            float4 a = ag4[an + chunk * 8 + j];
            float4 b = eg4[ae + chunk * 8 + j];
            int k = j * 4;
            zs[k + 0][tid] = a.x * b.x;
            zs[k + 1][tid] = a.y * b.y;
            zs[k + 2][tid] = a.z * b.z;
            zs[k + 3][tid] = a.w * b.w;
        }
        __syncthreads();
#pragma unroll 2
        for (int kl = 0; kl < 32; kl++) {
            ulonglong2 zA = *(const ulonglong2*)&zs[kl][tp * 8];      // p pairs 0-3
            ulonglong2 zB = *(const ulonglong2*)&zs[kl][tp * 8 + 4];  // p pairs 4-7... (2 u64 each)
            u64 zp[4] = {zA.x, zA.y, zB.x, zB.y};
            float4 w0 = *(const float4*)&ws[kl][th * 8];
            float4 w1 = *(const float4*)&ws[kl][th * 8 + 4];
            float wv[8] = {w0.x, w0.y, w0.z, w0.w, w1.x, w1.y, w1.z, w1.w};
#pragma unroll
            for (int j = 0; j < 8; j++) {
                u64 wd = pk2(wv[j], wv[j]);
#pragma unroll
                for (int i = 0; i < 4; i++)
                    acc2[i][j] = fma2(zp[i], wd, acc2[i][j]);
            }
        }
    }

    // epilogue: relu(+bm1) * Wm2, reduce over h
    float part[8];
#pragma unroll
    for (int i = 0; i < 8; i++) part[i] = 0.f;
#pragma unroll
    for (int j = 0; j < 8; j++) {
        float b = bm1[th * 8 + j];
        float w = Wm2[th * 8 + j];
#pragma unroll
        for (int i = 0; i < 4; i++) {
            float lo, hi;
            upk2(lo, hi, acc2[i][j]);
            part[i * 2 + 0] = fmaf(fmaxf(lo + b, 0.f), w, part[i * 2 + 0]);
            part[i * 2 + 1] = fmaf(fmaxf(hi + b, 0.f), w, part[i * 2 + 1]);
        }
    }
#pragma unroll
    for (int i = 0; i < 8; i++) red[tp * 8 + i][th] = part[i];
    __syncthreads();
    // cross-h reduce via second pass in smem
    {
        float v = bm2[0];
#pragma unroll
        for (int j = 0; j < 8; j++) v += red[tid][j];
        out[(size_t)Nn * Pp + q0 + tid] = v;
    }
}

// ---------------- host launcher ----------------
extern "C" void kernel_launch(void* const* d_in, const int* in_sizes, int n_in,
                              void* d_out, int out_size) {
    const float* nf  = (const float*)d_in[0];
    const float* W1  = (const float*)d_in[1];
    const float* b1  = (const float*)d_in[2];
    const float* W2  = (const float*)d_in[3];
    const float* b2  = (const float*)d_in[4];
    const float* Wt  = (const float*)d_in[5];
    const float* bt  = (const float*)d_in[6];
    const float* Wr  = (const float*)d_in[7];
    const float* br  = (const float*)d_in[8];
    const float* Wf  = (const float*)d_in[9];
    const float* bf  = (const float*)d_in[10];
    const float* Wna = (const float*)d_in[11];
    const float* bna = (const float*)d_in[12];
    const float* Wea = (const float*)d_in[13];
    const float* bea = (const float*)d_in[14];
    const float* Wm1 = (const float*)d_in[15];
    const float* bm1 = (const float*)d_in[16];
    const float* Wm2 = (const float*)d_in[17];
    const float* bm2 = (const float*)d_in[18];
    const int* node_idx = (const int*)d_in[19];
    const int* edge_idx = (const int*)d_in[20];
    const int* nni = (const int*)d_in[21];
    const int* nei = (const int*)d_in[22];
    float* out = (float*)d_out;

    // ---- CSR build ----
    k_zero<<<2048, 256>>>();
    k_count<<<(TNNZ + 255) / 256, 256>>>(node_idx, edge_idx);
    k_inv<<<(TN + 255) / 256, 256>>>();
    {
        int nbE = (TE + 4095) / 4096;
        k_scanA<0><<<nbE, 256>>>();
        k_scanB<<<1, 1024>>>(nbE);
        k_scanC<0><<<nbE, 256>>>();
    }
    {
        int nbN = (TN + 4095) / 4096;
        k_scanA<1><<<nbN, 256>>>();
        k_scanB<<<1, 1024>>>(nbN);
        k_scanC<1><<<nbN, 256>>>();
    }
    k_fill<<<(TNNZ + 255) / 256, 256>>>(node_idx, edge_idx);
    k_prep<<<(192 * 64 + 255) / 256, 256>>>(Wna, Wea);

    // ---- layer 1 ----
    k_xw1<<<(TN + 15) / 16, 256>>>(nf, W1, b1);
    k_eacc<0><<<(TE + 3) / 4, 256>>>();
    k_nacc<0><<<(TN + 3) / 4, 256>>>();

    // ---- layer 2 ----
    k_xw2<<<(TN + 15) / 16, 256>>>(W2, b2);
    k_eacc<1><<<(TE + 3) / 4, 256>>>();
    k_nacc<1><<<(TN + 3) / 4, 256>>>();

    // ---- heads ----
    k_node<<<Nn / GN, 256>>>(nf, bna, Wt, bt, Wr, br, Wf, bf, out);
    k_eagg<<<Ee / GN, 256>>>(bea);
    k_mlp<<<(2 * NNZn) / 128, 128>>>(node_idx, edge_idx, nni, nei, Wm1, bm1, Wm2, bm2, out);
}

// round 7
// speedup vs baseline: 3.5259x; 1.2223x over previous
#include <cuda_runtime.h>

#define Tt   12
#define Nn   100000
#define CINc 16
#define Ee   20000
#define NNZn 160000
#define Hh   64
#define Pp   12

#define TN   (Tt * Nn)
#define TE   (Tt * Ee)
#define TNNZ (Tt * NNZn)

typedef unsigned long long u64;

// ---- f32x2 packed helpers (Blackwell) ----
__device__ __forceinline__ u64 pk2(float lo, float hi) {
    u64 r;
    asm("mov.b64 %0, {%1, %2};" : "=l"(r) : "f"(lo), "f"(hi));
    return r;
}
__device__ __forceinline__ void upk2(float& lo, float& hi, u64 v) {
    asm("mov.b64 {%0, %1}, %2;" : "=f"(lo), "=f"(hi) : "l"(v));
}
__device__ __forceinline__ u64 fma2(u64 a, u64 b, u64 c) {
    u64 d;
    asm("fma.rn.f32x2 %0, %1, %2, %3;" : "=l"(d) : "l"(a), "l"(b), "l"(c));
    return d;
}

// ---------------- scratch ----------------
__device__ float g_xw[(size_t)TN * Hh];        // xw*dinv (layer 1 then layer 2)
__device__ float g_es[(size_t)TE * Hh];        // e2 (final edge emb)
__device__ float g_edge1[(size_t)TE * Hh];     // layer-1 edge accum
__device__ float g_agg[(size_t)Hh * Nn * 9];
__device__ float g_eagg[(size_t)Hh * Ee * 9];
__device__ float g_dinv[TN];
__device__ float g_binv[TE];
__device__ float g_wnat2[192 * 64];
__device__ float g_weat2[192 * 64];

__device__ int g_degN[TN];
__device__ int g_degE[TE];
__device__ int g_offN[TN + 1];
__device__ int g_offE[TE + 1];
__device__ int g_curN[TN];
__device__ int g_curE[TE];
__device__ int g_nlist[TNNZ];
__device__ int g_elist[TNNZ];
__device__ int g_part[1024];

// ---------------- zero ----------------
__global__ void k_zero() {
    int i = blockIdx.x * blockDim.x + threadIdx.x;
    int stride = gridDim.x * blockDim.x;
    for (int j = i; j < TN; j += stride) { g_degN[j] = 0; g_curN[j] = 0; }
    for (int j = i; j < TE; j += stride) { g_degE[j] = 0; g_curE[j] = 0; }
}

__global__ void k_count(const int* __restrict__ ni, const int* __restrict__ ei) {
    int i = blockIdx.x * blockDim.x + threadIdx.x;
    if (i >= TNNZ) return;
    int t = i / NNZn;
    atomicAdd(&g_degN[t * Nn + ni[i]], 1);
    atomicAdd(&g_degE[t * Ee + ei[i]], 1);
}

__global__ void k_inv() {
    int i = blockIdx.x * blockDim.x + threadIdx.x;
    if (i < TN) { int d = g_degN[i]; g_dinv[i] = d > 0 ? rsqrtf((float)d) : 0.f; }
    if (i < TE) { int c = g_degE[i]; g_binv[i] = c > 0 ? 1.f / (float)c : 0.f; }
}

// ---------------- scans ----------------
template <int SEL>
__global__ void k_scanA() {
    const int* cnt = SEL ? g_degN : g_degE;
    const int n = SEL ? TN : TE;
    __shared__ int sh[256];
    int b = blockIdx.x, t = threadIdx.x;
    int i0 = b * 4096 + t * 16;
    int s = 0;
#pragma unroll
    for (int k = 0; k < 16; k++) { int i = i0 + k; if (i < n) s += cnt[i]; }
    sh[t] = s; __syncthreads();
    for (int off = 128; off; off >>= 1) {
        if (t < off) sh[t] += sh[t + off];
        __syncthreads();
    }
    if (t == 0) g_part[b] = sh[0];
}

__global__ void k_scanB(int nb) {
    __shared__ int sh[1024];
    int t = threadIdx.x;
    int v = (t < nb) ? g_part[t] : 0;
    sh[t] = v; __syncthreads();
    for (int off = 1; off < 1024; off <<= 1) {
        int a = (t >= off) ? sh[t - off] : 0;
        __syncthreads();
        sh[t] += a;
        __syncthreads();
    }
    if (t < nb) g_part[t] = sh[t] - v;
}

template <int SEL>
__global__ void k_scanC() {
    const int* cnt = SEL ? g_degN : g_degE;
    int* off = SEL ? g_offN : g_offE;
    const int n = SEL ? TN : TE;
    __shared__ int sh[256];
    int b = blockIdx.x, t = threadIdx.x;
    int i0 = b * 4096 + t * 16;
    int loc[16]; int s = 0;
#pragma unroll
    for (int k = 0; k < 16; k++) {
        int i = i0 + k;
        loc[k] = (i < n) ? cnt[i] : 0;
        s += loc[k];
    }
    sh[t] = s; __syncthreads();
    for (int o = 1; o < 256; o <<= 1) {
        int a = (t >= o) ? sh[t - o] : 0;
        __syncthreads();
        sh[t] += a;
        __syncthreads();
    }
    int run = g_part[b] + sh[t] - s;
#pragma unroll
    for (int k = 0; k < 16; k++) {
        int i = i0 + k;
        if (i < n) {
            off[i] = run;
            run += loc[k];
            if (i == n - 1) off[n] = run;
        }
    }
}

__global__ void k_fill(const int* __restrict__ ni, const int* __restrict__ ei) {
    int i = blockIdx.x * blockDim.x + threadIdx.x;
    if (i >= TNNZ) return;
    int t = i / NNZn;
    int n = ni[i], e = ei[i];
    int se = t * Ee + e, sn = t * Nn + n;
    int pe = atomicAdd(&g_curE[se], 1);
    g_elist[g_offE[se] + pe] = n;
    int pn = atomicAdd(&g_curN[sn], 1);
    g_nlist[g_offN[sn] + pn] = e;
}

// ---------------- weight prep: packed channel-pair transposes ----------------
__global__ void k_prep(const float* __restrict__ Wna, const float* __restrict__ Wea) {
    int i = blockIdx.x * blockDim.x + threadIdx.x;
    if (i >= 192 * 64) return;
    int c = i / 192, i3 = i % 192;
    int cp = c & 31, hi = c >> 5;
    g_wnat2[(i3 * 32 + cp) * 2 + hi] = Wna[i];
    g_weat2[(i3 * 32 + cp) * 2 + hi] = Wea[i];
}

// ---------------- xw1 = (x @ W1 + b1) * dinv ----------------
__global__ void k_xw1(const float* __restrict__ nf, const float* __restrict__ W1,
                      const float* __restrict__ b1) {
    __shared__ float4 sW[16 * 16];
    __shared__ float sb[64];
    int tid = threadIdx.x;
    sW[tid] = ((const float4*)W1)[tid];
    if (tid < 64) sb[tid] = b1[tid];
    __syncthreads();
    int u = blockIdx.x * 16 + (tid >> 4);
    int c4 = tid & 15;
    if (u >= TN) return;
    float d = g_dinv[u];
    const float4* x4 = (const float4*)(nf + (size_t)u * CINc);
    float xv[16];
#pragma unroll
    for (int q = 0; q < 4; q++) {
        float4 v = x4[q];
        xv[q * 4 + 0] = v.x; xv[q * 4 + 1] = v.y; xv[q * 4 + 2] = v.z; xv[q * 4 + 3] = v.w;
    }
    u64 acc01 = pk2(sb[c4 * 4 + 0], sb[c4 * 4 + 1]);
    u64 acc23 = pk2(sb[c4 * 4 + 2], sb[c4 * 4 + 3]);
#pragma unroll
    for (int c = 0; c < 16; c++) {
        ulonglong2 w = *(const ulonglong2*)&sW[c * 16 + c4];
        u64 x2 = pk2(xv[c], xv[c]);
        acc01 = fma2(x2, w.x, acc01);
        acc23 = fma2(x2, w.y, acc23);
    }
    float4 r;
    upk2(r.x, r.y, acc01);
    upk2(r.z, r.w, acc23);
    r.x *= d; r.y *= d; r.z *= d; r.w *= d;
    ((float4*)g_xw)[(size_t)u * 16 + c4] = r;
}

// ---------------- edge segment sum ----------------
template <int LAYER>
__global__ void k_eacc() {
    int slot = blockIdx.x * 4 + (threadIdx.x >> 6);
    int h = threadIdx.x & 63;
    if (slot >= TE) return;
    int t = slot / Ee;
    int beg = g_offE[slot], end = g_offE[slot + 1];
    const float* base = g_xw + (size_t)t * Nn * Hh + h;
    float acc = 0.f;
    for (int j = beg; j < end; j++) {
        int n = g_elist[j];
        acc += __ldg(base + (size_t)n * Hh);
    }
    float* dst = (LAYER == 0) ? g_edge1 : g_es;
    dst[(size_t)slot * Hh + h] = acc * g_binv[slot];
}

// ---------------- FUSED node segsum (layer1) + xw2 GEMM ----------------
// block = 16 slots; phase1: 16 thr/slot gather h1 into smem; phase2: FFMA2 GEMM.
__global__ void __launch_bounds__(256) k_nx2(const float* __restrict__ W2,
                                             const float* __restrict__ b2) {
    __shared__ float4 sW[64 * 16];
    __shared__ float sX[16][65];
    __shared__ float sb[64];
    int tid = threadIdx.x;
    for (int j = tid; j < 1024; j += 256) sW[j] = ((const float4*)W2)[j];
    if (tid < 64) sb[tid] = b2[tid];
    int u0 = blockIdx.x * 16;
    // phase 1: gather h1 rows (g_edge1 already has binv folded); h1 = segsum * dinv
    {
        int sl = tid >> 4, q = tid & 15;
        int slot = u0 + sl;
        int t = slot / Nn;
        int beg = g_offN[slot], end = g_offN[slot + 1];
        float d = g_dinv[slot];
        const float4* src = (const float4*)(g_edge1 + (size_t)t * Ee * Hh) + q;
        float4 a = make_float4(0.f, 0.f, 0.f, 0.f);
        for (int j = beg; j < end; j++) {
            float4 v = __ldg(src + (size_t)g_nlist[j] * 16);
            a.x += v.x; a.y += v.y; a.z += v.z; a.w += v.w;
        }
        sX[sl][q * 4 + 0] = a.x * d;
        sX[sl][q * 4 + 1] = a.y * d;
        sX[sl][q * 4 + 2] = a.z * d;
        sX[sl][q * 4 + 3] = a.w * d;
    }
    __syncthreads();
    // phase 2: xw2 = (h1 @ W2 + b2) * dinv
    int g = tid >> 4, c4 = tid & 15;
    int u = u0 + g;
    u64 acc01 = pk2(sb[c4 * 4 + 0], sb[c4 * 4 + 1]);
    u64 acc23 = pk2(sb[c4 * 4 + 2], sb[c4 * 4 + 3]);
#pragma unroll 8
    for (int c = 0; c < 64; c++) {
        ulonglong2 w = *(const ulonglong2*)&sW[c * 16 + c4];
        float x = sX[g][c];
        u64 x2 = pk2(x, x);
        acc01 = fma2(x2, w.x, acc01);
        acc23 = fma2(x2, w.y, acc23);
    }
    float d = g_dinv[u];
    float4 r;
    upk2(r.x, r.y, acc01);
    upk2(r.z, r.w, acc23);
    r.x *= d; r.y *= d; r.z *= d; r.w *= d;
    ((float4*)g_xw)[(size_t)u * 16 + c4] = r;
}

// ---------------- per-node heads, FUSED with layer-2 node segsum ----------------
#define GN 8
#define CH 8
__global__ void __launch_bounds__(256) k_node(
        const float* __restrict__ nf,
        const float* __restrict__ bna,
        const float* __restrict__ Wt,  const float* __restrict__ bt,
        const float* __restrict__ Wr,  const float* __restrict__ br,
        const float* __restrict__ Wf,  const float* __restrict__ bf,
        float* __restrict__ out) {
    __shared__ float sx[GN][64][12];
    __shared__ u64 swc2[CH * 3 * 32];
    __shared__ float swt[3 * 192];
    __shared__ float swr[3 * 16];
    __shared__ float shv[GN][3][Tt];
    int tid = threadIdx.x;
    int g = tid >> 5, cp = tid & 31;
    int n = blockIdx.x * GN + g;

    // gather xs rows from g_es via node CSR (replaces g_xs materialization)
#pragma unroll
    for (int t = 0; t < Tt; t++) {
        int slot = t * Nn + n;
        int beg = g_offN[slot], end = g_offN[slot + 1];
        float d = g_dinv[slot];
        const float* src = g_es + (size_t)t * Ee * Hh;
        float a0 = 0.f, a1 = 0.f;
        for (int j = beg; j < end; j++) {
            const float* row = src + (size_t)g_nlist[j] * Hh;
            a0 += __ldg(row + cp);
            a1 += __ldg(row + cp + 32);
        }
        sx[g][cp][t]      = a0 * d;
        sx[g][cp + 32][t] = a1 * d;
    }
    for (int j = tid; j < 576; j += 256)
        swt[j] = Wt[(61 + j / 192) * 192 + (j % 192)];
    if (tid < 48) swr[tid] = Wr[(61 + tid / 16) * 16 + (tid % 16)];

    u64 acc2[9];
    {
        u64 b2 = pk2(bna[cp], bna[cp + 32]);
#pragma unroll
        for (int s = 0; s < 9; s++) acc2[s] = b2;
    }

    const u64* gw2 = (const u64*)g_wnat2;
    for (int chunk = 0; chunk < 64 / CH; chunk++) {
        __syncthreads();
        for (int j = tid; j < CH * 3 * 32; j += 256)
            swc2[j] = gw2[chunk * (CH * 3 * 32) + j];
        __syncthreads();
#pragma unroll
        for (int ii = 0; ii < CH; ii++) {
            int i = chunk * CH + ii;
            float4 x0 = *(const float4*)&sx[g][i][0];
            float4 x1 = *(const float4*)&sx[g][i][4];
            float4 x2 = *(const float4*)&sx[g][i][8];
            float xv[11] = {x0.x, x0.y, x0.z, x0.w, x1.x, x1.y, x1.z, x1.w,
                            x2.x, x2.y, x2.z};
            u64 xd[11];
#pragma unroll
            for (int s = 0; s < 11; s++) xd[s] = pk2(xv[s], xv[s]);
            u64 w0 = swc2[(ii * 3 + 0) * 32 + cp];
            u64 w1 = swc2[(ii * 3 + 1) * 32 + cp];
            u64 w2 = swc2[(ii * 3 + 2) * 32 + cp];
#pragma unroll
            for (int s = 0; s < 9; s++) {
                acc2[s] = fma2(w0, xd[s], acc2[s]);
                acc2[s] = fma2(w1, xd[s + 1], acc2[s]);
                acc2[s] = fma2(w2, xd[s + 2], acc2[s]);
            }
        }
    }
    {
        size_t b0 = ((size_t)cp * Nn + n) * 9;
        size_t b1 = ((size_t)(cp + 32) * Nn + n) * 9;
#pragma unroll
        for (int s = 0; s < 9; s++) {
            float lo, hi;
            upk2(lo, hi, acc2[s]);
            g_agg[b0 + s] = lo;
            g_agg[b1 + s] = hi;
        }
    }

    // indiv logit
    for (int u = tid; u < GN * 36; u += 256) {
        int gg = u / 36, r = u % 36;
        int o3 = r / Tt, t = r % Tt;
        int nn = blockIdx.x * GN + gg;
        float xp = bt[61 + o3];
#pragma unroll
        for (int dk = 0; dk < 3; dk++) {
            int tau = t + dk - 1;
            if (tau >= 0 && tau < Tt) {
                const float* wt = swt + o3 * 192 + dk;
#pragma unroll 8
                for (int i = 0; i < 64; i++) xp = fmaf(wt[i * 3], sx[gg][i][tau], xp);
            }
        }
        float rs = br[61 + o3];
        const float* xr = nf + ((size_t)t * Nn + nn) * CINc;
#pragma unroll
        for (int cc = 0; cc < CINc; cc++) rs = fmaf(swr[o3 * 16 + cc], xr[cc], rs);
        shv[gg][o3][t] = fmaxf(xp + rs, 0.f);
    }
    __syncthreads();
    if (tid < GN * Pp) {
        int gg = tid / Pp, pc = tid % Pp;
        int nn = blockIdx.x * GN + gg;
        float a = bf[pc];
#pragma unroll
        for (int t = 0; t < Tt; t++)
#pragma unroll
            for (int dk = 0; dk < 3; dk++)
                a = fmaf(Wf[pc * 36 + t * 3 + dk], shv[gg][dk][t], a);
        out[(size_t)nn * Pp + pc] = a;
    }
}

// ---------------- per-edge aggregator ----------------
__global__ void __launch_bounds__(256) k_eagg(const float* __restrict__ bea) {
    __shared__ float sx[GN][64][12];
    __shared__ u64 swc2[CH * 3 * 32];
    int tid = threadIdx.x;
    int g = tid >> 5, cp = tid & 31;
    int e = blockIdx.x * GN + g;

#pragma unroll
    for (int t = 0; t < 11; t++) {
        sx[g][cp][t]      = g_es[((size_t)t * Ee + e) * Hh + cp];
        sx[g][cp + 32][t] = g_es[((size_t)t * Ee + e) * Hh + cp + 32];
    }
    sx[g][cp][11] = 0.f;
    sx[g][cp + 32][11] = 0.f;

    u64 acc2[9];
    {
        u64 b2 = pk2(bea[cp], bea[cp + 32]);
#pragma unroll
        for (int s = 0; s < 9; s++) acc2[s] = b2;
    }

    const u64* gw2 = (const u64*)g_weat2;
    for (int chunk = 0; chunk < 64 / CH; chunk++) {
        __syncthreads();
        for (int j = tid; j < CH * 3 * 32; j += 256)
            swc2[j] = gw2[chunk * (CH * 3 * 32) + j];
        __syncthreads();
#pragma unroll
        for (int ii = 0; ii < CH; ii++) {
            int i = chunk * CH + ii;
            float4 x0 = *(const float4*)&sx[g][i][0];
            float4 x1 = *(const float4*)&sx[g][i][4];
            float4 x2 = *(const float4*)&sx[g][i][8];
            float xv[11] = {x0.x, x0.y, x0.z, x0.w, x1.x, x1.y, x1.z, x1.w,
                            x2.x, x2.y, x2.z};
            u64 xd[11];
#pragma unroll
            for (int s = 0; s < 11; s++) xd[s] = pk2(xv[s], xv[s]);
            u64 w0 = swc2[(ii * 3 + 0) * 32 + cp];
            u64 w1 = swc2[(ii * 3 + 1) * 32 + cp];
            u64 w2 = swc2[(ii * 3 + 2) * 32 + cp];
#pragma unroll
            for (int s = 0; s < 9; s++) {
                acc2[s] = fma2(w0, xd[s], acc2[s]);
                acc2[s] = fma2(w1, xd[s + 1], acc2[s]);
                acc2[s] = fma2(w2, xd[s + 2], acc2[s]);
            }
        }
    }
    size_t b0 = ((size_t)cp * Ee + e) * 9;
    size_t b1 = ((size_t)(cp + 32) * Ee + e) * 9;
#pragma unroll
    for (int s = 0; s < 9; s++) {
        float lo, hi;
        upk2(lo, hi, acc2[s]);
        g_eagg[b0 + s] = lo;
        g_eagg[b1 + s] = hi;
    }
}

// ---------------- score MLP ----------------
__global__ void __launch_bounds__(128) k_mlp(
        const int* __restrict__ ni_full, const int* __restrict__ ei_full,
        const int* __restrict__ nni, const int* __restrict__ nei,
        const float* __restrict__ Wm1, const float* __restrict__ bm1,
        const float* __restrict__ Wm2, const float* __restrict__ bm2,
        float* __restrict__ out) {
    __shared__ float zs[32][128];
    __shared__ float ws[32][64];
    __shared__ float red[128][9];
    __shared__ int sn[128], se[128];
    int tid = threadIdx.x;
    int q0 = blockIdx.x * 128;
    {
        int q = q0 + tid;
        int n, e;
        if (q < NNZn) { n = ni_full[11 * NNZn + q]; e = ei_full[11 * NNZn + q]; }
        else          { n = nni[q - NNZn];          e = nei[q - NNZn]; }
        sn[tid] = n; se[tid] = e;
    }
    __syncthreads();

    int tp = tid >> 3, th = tid & 7;
    u64 acc2[4][8];
#pragma unroll
    for (int i = 0; i < 4; i++)
#pragma unroll
        for (int j = 0; j < 8; j++) acc2[i][j] = 0;

    const float4* ag4 = (const float4*)g_agg;
    const float4* eg4 = (const float4*)g_eagg;
    const float4* wm4 = (const float4*)Wm1;
    int an = sn[tid] * 144, ae = se[tid] * 144;

    for (int chunk = 0; chunk < 18; chunk++) {
        __syncthreads();
        for (int j = tid; j < 512; j += 128)
            *((float4*)&ws[0][0] + j) = wm4[chunk * 512 + j];
#pragma unroll
        for (int j = 0; j < 8; j++) {
            float4 a = ag4[an + chunk * 8 + j];
            float4 b = eg4[ae + chunk * 8 + j];
            int k = j * 4;
            zs[k + 0][tid] = a.x * b.x;
            zs[k + 1][tid] = a.y * b.y;
            zs[k + 2][tid] = a.z * b.z;
            zs[k + 3][tid] = a.w * b.w;
        }
        __syncthreads();
#pragma unroll 2
        for (int kl = 0; kl < 32; kl++) {
            ulonglong2 zA = *(const ulonglong2*)&zs[kl][tp * 8];
            ulonglong2 zB = *(const ulonglong2*)&zs[kl][tp * 8 + 4];
            u64 zp[4] = {zA.x, zA.y, zB.x, zB.y};
            float4 w0 = *(const float4*)&ws[kl][th * 8];
            float4 w1 = *(const float4*)&ws[kl][th * 8 + 4];
            float wv[8] = {w0.x, w0.y, w0.z, w0.w, w1.x, w1.y, w1.z, w1.w};
#pragma unroll
            for (int j = 0; j < 8; j++) {
                u64 wd = pk2(wv[j], wv[j]);
#pragma unroll
                for (int i = 0; i < 4; i++)
                    acc2[i][j] = fma2(zp[i], wd, acc2[i][j]);
            }
        }
    }

    float part[8];
#pragma unroll
    for (int i = 0; i < 8; i++) part[i] = 0.f;
#pragma unroll
    for (int j = 0; j < 8; j++) {
        float b = bm1[th * 8 + j];
        float w = Wm2[th * 8 + j];
#pragma unroll
        for (int i = 0; i < 4; i++) {
            float lo, hi;
            upk2(lo, hi, acc2[i][j]);
            part[i * 2 + 0] = fmaf(fmaxf(lo + b, 0.f), w, part[i * 2 + 0]);
            part[i * 2 + 1] = fmaf(fmaxf(hi + b, 0.f), w, part[i * 2 + 1]);
        }
    }
#pragma unroll
    for (int i = 0; i < 8; i++) red[tp * 8 + i][th] = part[i];
    __syncthreads();
    {
        float v = bm2[0];
#pragma unroll
        for (int j = 0; j < 8; j++) v += red[tid][j];
        out[(size_t)Nn * Pp + q0 + tid] = v;
    }
}

// ---------------- host launcher ----------------
extern "C" void kernel_launch(void* const* d_in, const int* in_sizes, int n_in,
                              void* d_out, int out_size) {
    const float* nf  = (const float*)d_in[0];
    const float* W1  = (const float*)d_in[1];
    const float* b1  = (const float*)d_in[2];
    const float* W2  = (const float*)d_in[3];
    const float* b2  = (const float*)d_in[4];
    const float* Wt  = (const float*)d_in[5];
    const float* bt  = (const float*)d_in[6];
    const float* Wr  = (const float*)d_in[7];
    const float* br  = (const float*)d_in[8];
    const float* Wf  = (const float*)d_in[9];
    const float* bf  = (const float*)d_in[10];
    const float* Wna = (const float*)d_in[11];
    const float* bna = (const float*)d_in[12];
    const float* Wea = (const float*)d_in[13];
    const float* bea = (const float*)d_in[14];
    const float* Wm1 = (const float*)d_in[15];
    const float* bm1 = (const float*)d_in[16];
    const float* Wm2 = (const float*)d_in[17];
    const float* bm2 = (const float*)d_in[18];
    const int* node_idx = (const int*)d_in[19];
    const int* edge_idx = (const int*)d_in[20];
    const int* nni = (const int*)d_in[21];
    const int* nei = (const int*)d_in[22];
    float* out = (float*)d_out;

    int nbE = (TE + 4095) / 4096;
    int nbN = (TN + 4095) / 4096;

    // launches 1-5
    k_zero<<<2048, 256>>>();
    k_count<<<(TNNZ + 255) / 256, 256>>>(node_idx, edge_idx);
    k_inv<<<(TN + 255) / 256, 256>>>();
    k_scanA<0><<<nbE, 256>>>();
    k_scanB<<<1, 1024>>>(nbE);
    // launch 6 — profiled by ncu (-s 5 -c 1): the layer-1 GEMM
    k_xw1<<<(TN + 15) / 16, 256>>>(nf, W1, b1);
    // rest of CSR build
    k_scanC<0><<<nbE, 256>>>();
    k_scanA<1><<<nbN, 256>>>();
    k_scanB<<<1, 1024>>>(nbN);
    k_scanC<1><<<nbN, 256>>>();
    k_fill<<<(TNNZ + 255) / 256, 256>>>(node_idx, edge_idx);
    k_prep<<<(192 * 64 + 255) / 256, 256>>>(Wna, Wea);

    // layer 1 edge + fused node/xw2
    k_eacc<0><<<(TE + 3) / 4, 256>>>();
    k_nx2<<<TN / 16, 256>>>(W2, b2);

    // layer 2 edge
    k_eacc<1><<<(TE + 3) / 4, 256>>>();

    // heads (node segsum fused into k_node)
    k_node<<<Nn / GN, 256>>>(nf, bna, Wt, bt, Wr, br, Wf, bf, out);
    k_eagg<<<Ee / GN, 256>>>(bea);
    k_mlp<<<(2 * NNZn) / 128, 128>>>(node_idx, edge_idx, nni, nei, Wm1, bm1, Wm2, bm2, out);
}

// round 8
// speedup vs baseline: 3.9280x; 1.1141x over previous
#include <cuda_runtime.h>

#define Tt   12
#define Nn   100000
#define CINc 16
#define Ee   20000
#define NNZn 160000
#define Hh   64
#define Pp   12

#define TN   (Tt * Nn)
#define TE   (Tt * Ee)
#define TNNZ (Tt * NNZn)

typedef unsigned long long u64;

// ---- f32x2 packed helpers (Blackwell) ----
__device__ __forceinline__ u64 pk2(float lo, float hi) {
    u64 r;
    asm("mov.b64 %0, {%1, %2};" : "=l"(r) : "f"(lo), "f"(hi));
    return r;
}
__device__ __forceinline__ void upk2(float& lo, float& hi, u64 v) {
    asm("mov.b64 {%0, %1}, %2;" : "=f"(lo), "=f"(hi) : "l"(v));
}
__device__ __forceinline__ u64 fma2(u64 a, u64 b, u64 c) {
    u64 d;
    asm("fma.rn.f32x2 %0, %1, %2, %3;" : "=l"(d) : "l"(a), "l"(b), "l"(c));
    return d;
}

// ---------------- scratch ----------------
__device__ float g_xd[(size_t)TN * CINc];      // x * dinv  [t,n][16]
__device__ float g_es[(size_t)TE * Hh];        // e2 (final edge emb)
__device__ float g_edge1[(size_t)TE * Hh];     // layer-1 edge emb
__device__ float g_agg[(size_t)Hh * Nn * 9];
__device__ float g_eagg[(size_t)Hh * Ee * 9];
__device__ float g_dinv[TN];
__device__ float g_binv[TE];
__device__ float g_wnat2[192 * 64];
__device__ float g_weat2[192 * 64];

__device__ int g_degN[TN];
__device__ int g_degE[TE];
__device__ int g_offN[TN + 1];
__device__ int g_offE[TE + 1];
__device__ int g_curN[TN];
__device__ int g_curE[TE];
__device__ int g_nlist[TNNZ];
__device__ int g_elist[TNNZ];
__device__ int g_part[1024];

// ---------------- zero ----------------
__global__ void k_zero() {
    int i = blockIdx.x * blockDim.x + threadIdx.x;
    int stride = gridDim.x * blockDim.x;
    for (int j = i; j < TN; j += stride) { g_degN[j] = 0; g_curN[j] = 0; }
    for (int j = i; j < TE; j += stride) { g_degE[j] = 0; g_curE[j] = 0; }
}

__global__ void k_count(const int* __restrict__ ni, const int* __restrict__ ei) {
    int i = blockIdx.x * blockDim.x + threadIdx.x;
    if (i >= TNNZ) return;
    int t = i / NNZn;
    atomicAdd(&g_degN[t * Nn + ni[i]], 1);
    atomicAdd(&g_degE[t * Ee + ei[i]], 1);
}

__global__ void k_inv() {
    int i = blockIdx.x * blockDim.x + threadIdx.x;
    if (i < TN) { int d = g_degN[i]; g_dinv[i] = d > 0 ? rsqrtf((float)d) : 0.f; }
    if (i < TE) { int c = g_degE[i]; g_binv[i] = c > 0 ? 1.f / (float)c : 0.f; }
}

// ---------------- xd = x * dinv ----------------
__global__ void k_xd(const float* __restrict__ nf) {
    int gi = blockIdx.x * blockDim.x + threadIdx.x;
    if (gi >= TN * 4) return;
    int u = gi >> 2, q = gi & 3;
    float d = g_dinv[u];
    float4 v = ((const float4*)nf)[(size_t)u * 4 + q];
    v.x *= d; v.y *= d; v.z *= d; v.w *= d;
    ((float4*)g_xd)[(size_t)u * 4 + q] = v;
}

// ---------------- scans ----------------
template <int SEL>
__global__ void k_scanA() {
    const int* cnt = SEL ? g_degN : g_degE;
    const int n = SEL ? TN : TE;
    __shared__ int sh[256];
    int b = blockIdx.x, t = threadIdx.x;
    int i0 = b * 4096 + t * 16;
    int s = 0;
#pragma unroll
    for (int k = 0; k < 16; k++) { int i = i0 + k; if (i < n) s += cnt[i]; }
    sh[t] = s; __syncthreads();
    for (int off = 128; off; off >>= 1) {
        if (t < off) sh[t] += sh[t + off];
        __syncthreads();
    }
    if (t == 0) g_part[b] = sh[0];
}

__global__ void k_scanB(int nb) {
    __shared__ int sh[1024];
    int t = threadIdx.x;
    int v = (t < nb) ? g_part[t] : 0;
    sh[t] = v; __syncthreads();
    for (int off = 1; off < 1024; off <<= 1) {
        int a = (t >= off) ? sh[t - off] : 0;
        __syncthreads();
        sh[t] += a;
        __syncthreads();
    }
    if (t < nb) g_part[t] = sh[t] - v;
}

template <int SEL>
__global__ void k_scanC() {
    const int* cnt = SEL ? g_degN : g_degE;
    int* off = SEL ? g_offN : g_offE;
    const int n = SEL ? TN : TE;
    __shared__ int sh[256];
    int b = blockIdx.x, t = threadIdx.x;
    int i0 = b * 4096 + t * 16;
    int loc[16]; int s = 0;
#pragma unroll
    for (int k = 0; k < 16; k++) {
        int i = i0 + k;
        loc[k] = (i < n) ? cnt[i] : 0;
        s += loc[k];
    }
    sh[t] = s; __syncthreads();
    for (int o = 1; o < 256; o <<= 1) {
        int a = (t >= o) ? sh[t - o] : 0;
        __syncthreads();
        sh[t] += a;
        __syncthreads();
    }
    int run = g_part[b] + sh[t] - s;
#pragma unroll
    for (int k = 0; k < 16; k++) {
        int i = i0 + k;
        if (i < n) {
            off[i] = run;
            run += loc[k];
            if (i == n - 1) off[n] = run;
        }
    }
}

__global__ void k_fill(const int* __restrict__ ni, const int* __restrict__ ei) {
    int i = blockIdx.x * blockDim.x + threadIdx.x;
    if (i >= TNNZ) return;
    int t = i / NNZn;
    int n = ni[i], e = ei[i];
    int se = t * Ee + e, sn = t * Nn + n;
    int pe = atomicAdd(&g_curE[se], 1);
    g_elist[g_offE[se] + pe] = n;
    int pn = atomicAdd(&g_curN[sn], 1);
    g_nlist[g_offN[sn] + pn] = e;
}

// ---------------- weight prep ----------------
__global__ void k_prep(const float* __restrict__ Wna, const float* __restrict__ Wea) {
    int i = blockIdx.x * blockDim.x + threadIdx.x;
    if (i >= 192 * 64) return;
    int c = i / 192, i3 = i % 192;
    int cp = c & 31, hi = c >> 5;
    g_wnat2[(i3 * 32 + cp) * 2 + hi] = Wna[i];
    g_weat2[(i3 * 32 + cp) * 2 + hi] = Wea[i];
}

// ---------------- layer 1 edge emb: edge1 = binv*(X_e @ W1 + s_e*b1) ----------------
__global__ void __launch_bounds__(256) k_e1(const float* __restrict__ W1,
                                            const float* __restrict__ b1) {
    __shared__ float sW1[16 * 64];
    __shared__ float sX[4][17];
    int tid = threadIdx.x;
    for (int j = tid; j < 1024; j += 256) sW1[j] = W1[j];
    int sl = tid >> 6, q = tid & 63;
    int slot = blockIdx.x * 4 + sl;
    int t = slot / Ee;
    int beg = g_offE[slot], end = g_offE[slot + 1];
    if (q < 16) {
        float a = 0.f;
        for (int j = beg; j < end; j++)
            a += __ldg(g_xd + (size_t)(t * Nn + g_elist[j]) * 16 + q);
        sX[sl][q] = a;
    } else if (q == 16) {
        float s = 0.f;
        for (int j = beg; j < end; j++)
            s += __ldg(g_dinv + t * Nn + g_elist[j]);
        sX[sl][16] = s;
    }
    __syncthreads();
    float acc = sX[sl][16] * b1[q];
#pragma unroll
    for (int c = 0; c < 16; c++)
        acc = fmaf(sX[sl][c], sW1[c * 64 + q], acc);
    g_edge1[(size_t)slot * Hh + q] = acc * g_binv[slot];
}

// ---------------- layer 2 edge emb: es = binv*(V_e @ W2 + s2_e*b2) ----------------
// V_e = sum_{n in e} dinv_n^2 * sum_{e' in n} edge1[e']
__global__ void __launch_bounds__(256) k_es2(const float* __restrict__ W2,
                                             const float* __restrict__ b2) {
    __shared__ float sW2[64 * 64];   // 16 KB
    __shared__ float sV[4][65];
    __shared__ float ss2[4];
    int tid = threadIdx.x;
    for (int j = tid; j < 4096; j += 256) sW2[j] = W2[j];
    int sl = tid >> 6, h = tid & 63;
    int slot = blockIdx.x * 4 + sl;
    int t = slot / Ee;
    int beg = g_offE[slot], end = g_offE[slot + 1];
    const float* e1base = g_edge1 + (size_t)t * Ee * Hh + h;
    float acc = 0.f;
    float s2 = 0.f;
    for (int j = beg; j < end; j++) {
        int n = g_elist[j];
        int sn = t * Nn + n;
        float d = __ldg(g_dinv + sn);
        float d2 = d * d;
        s2 += d;
        int nb = g_offN[sn], ne = g_offN[sn + 1];
        for (int jj = nb; jj < ne; jj++) {
            int ep = g_nlist[jj];
            acc = fmaf(d2, __ldg(e1base + (size_t)ep * Hh), acc);
        }
    }
    sV[sl][h] = acc;
    if (h == 0) ss2[sl] = s2;
    __syncthreads();
    float r = ss2[sl] * b2[h];
#pragma unroll 8
    for (int c = 0; c < 64; c++)
        r = fmaf(sV[sl][c], sW2[c * 64 + h], r);
    g_es[(size_t)slot * Hh + h] = r * g_binv[slot];
}

// ---------------- per-node heads (xs gathered from g_es via CSR) ----------------
#define GN 8
#define CH 8
__global__ void __launch_bounds__(256) k_node(
        const float* __restrict__ nf,
        const float* __restrict__ bna,
        const float* __restrict__ Wt,  const float* __restrict__ bt,
        const float* __restrict__ Wr,  const float* __restrict__ br,
        const float* __restrict__ Wf,  const float* __restrict__ bf,
        float* __restrict__ out) {
    __shared__ float sx[GN][64][12];
    __shared__ u64 swc2[CH * 3 * 32];
    __shared__ float swt[3 * 192];
    __shared__ float swr[3 * 16];
    __shared__ float shv[GN][3][Tt];
    int tid = threadIdx.x;
    int g = tid >> 5, cp = tid & 31;
    int n = blockIdx.x * GN + g;

#pragma unroll
    for (int t = 0; t < Tt; t++) {
        int slot = t * Nn + n;
        int beg = g_offN[slot], end = g_offN[slot + 1];
        float d = g_dinv[slot];
        const float* src = g_es + (size_t)t * Ee * Hh;
        float a0 = 0.f, a1 = 0.f;
        for (int j = beg; j < end; j++) {
            const float* row = src + (size_t)g_nlist[j] * Hh;
            a0 += __ldg(row + cp);
            a1 += __ldg(row + cp + 32);
        }
        sx[g][cp][t]      = a0 * d;
        sx[g][cp + 32][t] = a1 * d;
    }
    for (int j = tid; j < 576; j += 256)
        swt[j] = Wt[(61 + j / 192) * 192 + (j % 192)];
    if (tid < 48) swr[tid] = Wr[(61 + tid / 16) * 16 + (tid % 16)];

    u64 acc2[9];
    {
        u64 b2 = pk2(bna[cp], bna[cp + 32]);
#pragma unroll
        for (int s = 0; s < 9; s++) acc2[s] = b2;
    }

    const u64* gw2 = (const u64*)g_wnat2;
    for (int chunk = 0; chunk < 64 / CH; chunk++) {
        __syncthreads();
        for (int j = tid; j < CH * 3 * 32; j += 256)
            swc2[j] = gw2[chunk * (CH * 3 * 32) + j];
        __syncthreads();
#pragma unroll
        for (int ii = 0; ii < CH; ii++) {
            int i = chunk * CH + ii;
            float4 x0 = *(const float4*)&sx[g][i][0];
            float4 x1 = *(const float4*)&sx[g][i][4];
            float4 x2 = *(const float4*)&sx[g][i][8];
            float xv[11] = {x0.x, x0.y, x0.z, x0.w, x1.x, x1.y, x1.z, x1.w,
                            x2.x, x2.y, x2.z};
            u64 xd[11];
#pragma unroll
            for (int s = 0; s < 11; s++) xd[s] = pk2(xv[s], xv[s]);
            u64 w0 = swc2[(ii * 3 + 0) * 32 + cp];
            u64 w1 = swc2[(ii * 3 + 1) * 32 + cp];
            u64 w2 = swc2[(ii * 3 + 2) * 32 + cp];
#pragma unroll
            for (int s = 0; s < 9; s++) {
                acc2[s] = fma2(w0, xd[s], acc2[s]);
                acc2[s] = fma2(w1, xd[s + 1], acc2[s]);
                acc2[s] = fma2(w2, xd[s + 2], acc2[s]);
            }
        }
    }
    {
        size_t b0 = ((size_t)cp * Nn + n) * 9;
        size_t b1 = ((size_t)(cp + 32) * Nn + n) * 9;
#pragma unroll
        for (int s = 0; s < 9; s++) {
            float lo, hi;
            upk2(lo, hi, acc2[s]);
            g_agg[b0 + s] = lo;
            g_agg[b1 + s] = hi;
        }
    }

    for (int u = tid; u < GN * 36; u += 256) {
        int gg = u / 36, r = u % 36;
        int o3 = r / Tt, t = r % Tt;
        int nn = blockIdx.x * GN + gg;
        float xp = bt[61 + o3];
#pragma unroll
        for (int dk = 0; dk < 3; dk++) {
            int tau = t + dk - 1;
            if (tau >= 0 && tau < Tt) {
                const float* wt = swt + o3 * 192 + dk;
#pragma unroll 8
                for (int i = 0; i < 64; i++) xp = fmaf(wt[i * 3], sx[gg][i][tau], xp);
            }
        }
        float rs = br[61 + o3];
        const float* xr = nf + ((size_t)t * Nn + nn) * CINc;
#pragma unroll
        for (int cc = 0; cc < CINc; cc++) rs = fmaf(swr[o3 * 16 + cc], xr[cc], rs);
        shv[gg][o3][t] = fmaxf(xp + rs, 0.f);
    }
    __syncthreads();
    if (tid < GN * Pp) {
        int gg = tid / Pp, pc = tid % Pp;
        int nn = blockIdx.x * GN + gg;
        float a = bf[pc];
#pragma unroll
        for (int t = 0; t < Tt; t++)
#pragma unroll
            for (int dk = 0; dk < 3; dk++)
                a = fmaf(Wf[pc * 36 + t * 3 + dk], shv[gg][dk][t], a);
        out[(size_t)nn * Pp + pc] = a;
    }
}

// ---------------- per-edge aggregator ----------------
__global__ void __launch_bounds__(256) k_eagg(const float* __restrict__ bea) {
    __shared__ float sx[GN][64][12];
    __shared__ u64 swc2[CH * 3 * 32];
    int tid = threadIdx.x;
    int g = tid >> 5, cp = tid & 31;
    int e = blockIdx.x * GN + g;

#pragma unroll
    for (int t = 0; t < 11; t++) {
        sx[g][cp][t]      = g_es[((size_t)t * Ee + e) * Hh + cp];
        sx[g][cp + 32][t] = g_es[((size_t)t * Ee + e) * Hh + cp + 32];
    }
    sx[g][cp][11] = 0.f;
    sx[g][cp + 32][11] = 0.f;

    u64 acc2[9];
    {
        u64 b2 = pk2(bea[cp], bea[cp + 32]);
#pragma unroll
        for (int s = 0; s < 9; s++) acc2[s] = b2;
    }

    const u64* gw2 = (const u64*)g_weat2;
    for (int chunk = 0; chunk < 64 / CH; chunk++) {
        __syncthreads();
        for (int j = tid; j < CH * 3 * 32; j += 256)
            swc2[j] = gw2[chunk * (CH * 3 * 32) + j];
        __syncthreads();
#pragma unroll
        for (int ii = 0; ii < CH; ii++) {
            int i = chunk * CH + ii;
            float4 x0 = *(const float4*)&sx[g][i][0];
            float4 x1 = *(const float4*)&sx[g][i][4];
            float4 x2 = *(const float4*)&sx[g][i][8];
            float xv[11] = {x0.x, x0.y, x0.z, x0.w, x1.x, x1.y, x1.z, x1.w,
                            x2.x, x2.y, x2.z};
            u64 xd[11];
#pragma unroll
            for (int s = 0; s < 11; s++) xd[s] = pk2(xv[s], xv[s]);
            u64 w0 = swc2[(ii * 3 + 0) * 32 + cp];
            u64 w1 = swc2[(ii * 3 + 1) * 32 + cp];
            u64 w2 = swc2[(ii * 3 + 2) * 32 + cp];
#pragma unroll
            for (int s = 0; s < 9; s++) {
                acc2[s] = fma2(w0, xd[s], acc2[s]);
                acc2[s] = fma2(w1, xd[s + 1], acc2[s]);
                acc2[s] = fma2(w2, xd[s + 2], acc2[s]);
            }
        }
    }
    size_t b0 = ((size_t)cp * Ee + e) * 9;
    size_t b1 = ((size_t)(cp + 32) * Ee + e) * 9;
#pragma unroll
    for (int s = 0; s < 9; s++) {
        float lo, hi;
        upk2(lo, hi, acc2[s]);
        g_eagg[b0 + s] = lo;
        g_eagg[b1 + s] = hi;
    }
}

// ---------------- score MLP ----------------
__global__ void __launch_bounds__(128) k_mlp(
        const int* __restrict__ ni_full, const int* __restrict__ ei_full,
        const int* __restrict__ nni, const int* __restrict__ nei,
        const float* __restrict__ Wm1, const float* __restrict__ bm1,
        const float* __restrict__ Wm2, const float* __restrict__ bm2,
        float* __restrict__ out) {
    __shared__ float zs[32][128];
    __shared__ float ws[32][64];
    __shared__ float red[128][9];
    __shared__ int sn[128], se[128];
    int tid = threadIdx.x;
    int q0 = blockIdx.x * 128;
    {
        int q = q0 + tid;
        int n, e;
        if (q < NNZn) { n = ni_full[11 * NNZn + q]; e = ei_full[11 * NNZn + q]; }
        else          { n = nni[q - NNZn];          e = nei[q - NNZn]; }
        sn[tid] = n; se[tid] = e;
    }
    __syncthreads();

    int tp = tid >> 3, th = tid & 7;
    u64 acc2[4][8];
#pragma unroll
    for (int i = 0; i < 4; i++)
#pragma unroll
        for (int j = 0; j < 8; j++) acc2[i][j] = 0;

    const float4* ag4 = (const float4*)g_agg;
    const float4* eg4 = (const float4*)g_eagg;
    const float4* wm4 = (const float4*)Wm1;
    int an = sn[tid] * 144, ae = se[tid] * 144;

    for (int chunk = 0; chunk < 18; chunk++) {
        __syncthreads();
        for (int j = tid; j < 512; j += 128)
            *((float4*)&ws[0][0] + j) = wm4[chunk * 512 + j];
#pragma unroll
        for (int j = 0; j < 8; j++) {
            float4 a = ag4[an + chunk * 8 + j];
            float4 b = eg4[ae + chunk * 8 + j];
            int k = j * 4;
            zs[k + 0][tid] = a.x * b.x;
            zs[k + 1][tid] = a.y * b.y;
            zs[k + 2][tid] = a.z * b.z;
            zs[k + 3][tid] = a.w * b.w;
        }
        __syncthreads();
#pragma unroll 2
        for (int kl = 0; kl < 32; kl++) {
            ulonglong2 zA = *(const ulonglong2*)&zs[kl][tp * 8];
            ulonglong2 zB = *(const ulonglong2*)&zs[kl][tp * 8 + 4];
            u64 zp[4] = {zA.x, zA.y, zB.x, zB.y};
            float4 w0 = *(const float4*)&ws[kl][th * 8];
            float4 w1 = *(const float4*)&ws[kl][th * 8 + 4];
            float wv[8] = {w0.x, w0.y, w0.z, w0.w, w1.x, w1.y, w1.z, w1.w};
#pragma unroll
            for (int j = 0; j < 8; j++) {
                u64 wd = pk2(wv[j], wv[j]);
#pragma unroll
                for (int i = 0; i < 4; i++)
                    acc2[i][j] = fma2(zp[i], wd, acc2[i][j]);
            }
        }
    }

    float part[8];
#pragma unroll
    for (int i = 0; i < 8; i++) part[i] = 0.f;
#pragma unroll
    for (int j = 0; j < 8; j++) {
        float b = bm1[th * 8 + j];
        float w = Wm2[th * 8 + j];
#pragma unroll
        for (int i = 0; i < 4; i++) {
            float lo, hi;
            upk2(lo, hi, acc2[i][j]);
            part[i * 2 + 0] = fmaf(fmaxf(lo + b, 0.f), w, part[i * 2 + 0]);
            part[i * 2 + 1] = fmaf(fmaxf(hi + b, 0.f), w, part[i * 2 + 1]);
        }
    }
#pragma unroll
    for (int i = 0; i < 8; i++) red[tp * 8 + i][th] = part[i];
    __syncthreads();
    {
        float v = bm2[0];
#pragma unroll
        for (int j = 0; j < 8; j++) v += red[tid][j];
        out[(size_t)Nn * Pp + q0 + tid] = v;
    }
}

// ---------------- host launcher ----------------
extern "C" void kernel_launch(void* const* d_in, const int* in_sizes, int n_in,
                              void* d_out, int out_size) {
    const float* nf  = (const float*)d_in[0];
    const float* W1  = (const float*)d_in[1];
    const float* b1  = (const float*)d_in[2];
    const float* W2  = (const float*)d_in[3];
    const float* b2  = (const float*)d_in[4];
    const float* Wt  = (const float*)d_in[5];
    const float* bt  = (const float*)d_in[6];
    const float* Wr  = (const float*)d_in[7];
    const float* br  = (const float*)d_in[8];
    const float* Wf  = (const float*)d_in[9];
    const float* bf  = (const float*)d_in[10];
    const float* Wna = (const float*)d_in[11];
    const float* bna = (const float*)d_in[12];
    const float* Wea = (const float*)d_in[13];
    const float* bea = (const float*)d_in[14];
    const float* Wm1 = (const float*)d_in[15];
    const float* bm1 = (const float*)d_in[16];
    const float* Wm2 = (const float*)d_in[17];
    const float* bm2 = (const float*)d_in[18];
    const int* node_idx = (const int*)d_in[19];
    const int* edge_idx = (const int*)d_in[20];
    const int* nni = (const int*)d_in[21];
    const int* nei = (const int*)d_in[22];
    float* out = (float*)d_out;

    int nbE = (TE + 4095) / 4096;
    int nbN = (TN + 4095) / 4096;

    k_zero<<<2048, 256>>>();
    k_count<<<(TNNZ + 255) / 256, 256>>>(node_idx, edge_idx);
    k_inv<<<(TN + 255) / 256, 256>>>();
    k_xd<<<(TN * 4 + 255) / 256, 256>>>(nf);
    k_scanA<0><<<nbE, 256>>>();
    k_scanB<<<1, 1024>>>(nbE);
    k_scanC<0><<<nbE, 256>>>();
    k_scanA<1><<<nbN, 256>>>();
    k_scanB<<<1, 1024>>>(nbN);
    k_scanC<1><<<nbN, 256>>>();
    k_fill<<<(TNNZ + 255) / 256, 256>>>(node_idx, edge_idx);
    k_prep<<<(192 * 64 + 255) / 256, 256>>>(Wna, Wea);

    // layer 1 (edge-side GEMM after linear segsum)
    k_e1<<<TE / 4, 256>>>(W1, b1);
    // layer 2 (double-gather + edge-side GEMM)
    k_es2<<<TE / 4, 256>>>(W2, b2);

    // heads
    k_node<<<Nn / GN, 256>>>(nf, bna, Wt, bt, Wr, br, Wf, bf, out);
    k_eagg<<<Ee / GN, 256>>>(bea);
    k_mlp<<<(2 * NNZn) / 128, 128>>>(node_idx, edge_idx, nni, nei, Wm1, bm1, Wm2, bm2, out);
}

// round 9
// speedup vs baseline: 3.9884x; 1.0154x over previous
#include <cuda_runtime.h>

#define Tt   12
#define Nn   100000
#define CINc 16
#define Ee   20000
#define NNZn 160000
#define Hh   64
#define Pp   12

#define TN   (Tt * Nn)
#define TE   (Tt * Ee)
#define TNNZ (Tt * NNZn)

typedef unsigned long long u64;

// ---- f32x2 packed helpers (Blackwell) ----
__device__ __forceinline__ u64 pk2(float lo, float hi) {
    u64 r;
    asm("mov.b64 %0, {%1, %2};" : "=l"(r) : "f"(lo), "f"(hi));
    return r;
}
__device__ __forceinline__ void upk2(float& lo, float& hi, u64 v) {
    asm("mov.b64 {%0, %1}, %2;" : "=f"(lo), "=f"(hi) : "l"(v));
}
__device__ __forceinline__ u64 fma2(u64 a, u64 b, u64 c) {
    u64 d;
    asm("fma.rn.f32x2 %0, %1, %2, %3;" : "=l"(d) : "l"(a), "l"(b), "l"(c));
    return d;
}
// ---- tf32 helpers ----
__device__ __forceinline__ unsigned f2tf(float f) {
    unsigned r;
    asm("cvt.rna.tf32.f32 %0, %1;" : "=r"(r) : "f"(f));
    return r;
}
__device__ __forceinline__ void mma_tf32(float& c0, float& c1, float& c2, float& c3,
                                         unsigned a0, unsigned a1, unsigned a2, unsigned a3,
                                         unsigned b0, unsigned b1) {
    asm volatile(
        "mma.sync.aligned.m16n8k8.row.col.f32.tf32.tf32.f32 "
        "{%0,%1,%2,%3}, {%4,%5,%6,%7}, {%8,%9}, {%0,%1,%2,%3};"
        : "+f"(c0), "+f"(c1), "+f"(c2), "+f"(c3)
        : "r"(a0), "r"(a1), "r"(a2), "r"(a3), "r"(b0), "r"(b1));
}

// ---------------- scratch ----------------
__device__ float g_xd[(size_t)TN * CINc];
__device__ float g_es[(size_t)TE * Hh];
__device__ float g_edge1[(size_t)TE * Hh];
__device__ float g_agg[(size_t)Hh * Nn * 9];
__device__ float g_eagg[(size_t)Hh * Ee * 9];
__device__ float g_dinv[TN];
__device__ float g_binv[TE];
__device__ float g_wnat2[192 * 64];
__device__ float g_weat2[192 * 64];

__device__ int g_degN[TN];
__device__ int g_degE[TE];
__device__ int g_offN[TN + 1];
__device__ int g_offE[TE + 1];
__device__ int g_curN[TN];
__device__ int g_curE[TE];
__device__ int g_nlist[TNNZ];
__device__ int g_elist[TNNZ];
__device__ int g_part[1024];

// ---------------- zero ----------------
__global__ void k_zero() {
    int i = blockIdx.x * blockDim.x + threadIdx.x;
    int stride = gridDim.x * blockDim.x;
    for (int j = i; j < TN; j += stride) { g_degN[j] = 0; g_curN[j] = 0; }
    for (int j = i; j < TE; j += stride) { g_degE[j] = 0; g_curE[j] = 0; }
}

__global__ void k_count(const int* __restrict__ ni, const int* __restrict__ ei) {
    int i = blockIdx.x * blockDim.x + threadIdx.x;
    if (i >= TNNZ) return;
    int t = i / NNZn;
    atomicAdd(&g_degN[t * Nn + ni[i]], 1);
    atomicAdd(&g_degE[t * Ee + ei[i]], 1);
}

__global__ void k_inv() {
    int i = blockIdx.x * blockDim.x + threadIdx.x;
    if (i < TN) { int d = g_degN[i]; g_dinv[i] = d > 0 ? rsqrtf((float)d) : 0.f; }
    if (i < TE) { int c = g_degE[i]; g_binv[i] = c > 0 ? 1.f / (float)c : 0.f; }
}

// ---------------- xd = x * dinv ----------------
__global__ void k_xd(const float* __restrict__ nf) {
    int gi = blockIdx.x * blockDim.x + threadIdx.x;
    if (gi >= TN * 4) return;
    int u = gi >> 2, q = gi & 3;
    float d = g_dinv[u];
    float4 v = ((const float4*)nf)[(size_t)u * 4 + q];
    v.x *= d; v.y *= d; v.z *= d; v.w *= d;
    ((float4*)g_xd)[(size_t)u * 4 + q] = v;
}

// ---------------- scans ----------------
template <int SEL>
__global__ void k_scanA() {
    const int* cnt = SEL ? g_degN : g_degE;
    const int n = SEL ? TN : TE;
    __shared__ int sh[256];
    int b = blockIdx.x, t = threadIdx.x;
    int i0 = b * 4096 + t * 16;
    int s = 0;
#pragma unroll
    for (int k = 0; k < 16; k++) { int i = i0 + k; if (i < n) s += cnt[i]; }
    sh[t] = s; __syncthreads();
    for (int off = 128; off; off >>= 1) {
        if (t < off) sh[t] += sh[t + off];
        __syncthreads();
    }
    if (t == 0) g_part[b] = sh[0];
}

__global__ void k_scanB(int nb) {
    __shared__ int sh[1024];
    int t = threadIdx.x;
    int v = (t < nb) ? g_part[t] : 0;
    sh[t] = v; __syncthreads();
    for (int off = 1; off < 1024; off <<= 1) {
        int a = (t >= off) ? sh[t - off] : 0;
        __syncthreads();
        sh[t] += a;
        __syncthreads();
    }
    if (t < nb) g_part[t] = sh[t] - v;
}

template <int SEL>
__global__ void k_scanC() {
    const int* cnt = SEL ? g_degN : g_degE;
    int* off = SEL ? g_offN : g_offE;
    const int n = SEL ? TN : TE;
    __shared__ int sh[256];
    int b = blockIdx.x, t = threadIdx.x;
    int i0 = b * 4096 + t * 16;
    int loc[16]; int s = 0;
#pragma unroll
    for (int k = 0; k < 16; k++) {
        int i = i0 + k;
        loc[k] = (i < n) ? cnt[i] : 0;
        s += loc[k];
    }
    sh[t] = s; __syncthreads();
    for (int o = 1; o < 256; o <<= 1) {
        int a = (t >= o) ? sh[t - o] : 0;
        __syncthreads();
        sh[t] += a;
        __syncthreads();
    }
    int run = g_part[b] + sh[t] - s;
#pragma unroll
    for (int k = 0; k < 16; k++) {
        int i = i0 + k;
        if (i < n) {
            off[i] = run;
            run += loc[k];
            if (i == n - 1) off[n] = run;
        }
    }
}

__global__ void k_fill(const int* __restrict__ ni, const int* __restrict__ ei) {
    int i = blockIdx.x * blockDim.x + threadIdx.x;
    if (i >= TNNZ) return;
    int t = i / NNZn;
    int n = ni[i], e = ei[i];
    int se = t * Ee + e, sn = t * Nn + n;
    int pe = atomicAdd(&g_curE[se], 1);
    g_elist[g_offE[se] + pe] = n;
    int pn = atomicAdd(&g_curN[sn], 1);
    g_nlist[g_offN[sn] + pn] = e;
}

// ---------------- weight prep ----------------
__global__ void k_prep(const float* __restrict__ Wna, const float* __restrict__ Wea) {
    int i = blockIdx.x * blockDim.x + threadIdx.x;
    if (i >= 192 * 64) return;
    int c = i / 192, i3 = i % 192;
    int cp = c & 31, hi = c >> 5;
    g_wnat2[(i3 * 32 + cp) * 2 + hi] = Wna[i];
    g_weat2[(i3 * 32 + cp) * 2 + hi] = Wea[i];
}

// ---------------- layer 1 edge emb ----------------
__global__ void __launch_bounds__(256) k_e1(const float* __restrict__ W1,
                                            const float* __restrict__ b1) {
    __shared__ float sW1[16 * 64];
    __shared__ float sX[4][17];
    int tid = threadIdx.x;
    for (int j = tid; j < 1024; j += 256) sW1[j] = W1[j];
    int sl = tid >> 6, q = tid & 63;
    int slot = blockIdx.x * 4 + sl;
    int t = slot / Ee;
    int beg = g_offE[slot], end = g_offE[slot + 1];
    if (q < 16) {
        float a = 0.f;
        for (int j = beg; j < end; j++)
            a += __ldg(g_xd + (size_t)(t * Nn + g_elist[j]) * 16 + q);
        sX[sl][q] = a;
    } else if (q == 16) {
        float s = 0.f;
        for (int j = beg; j < end; j++)
            s += __ldg(g_dinv + t * Nn + g_elist[j]);
        sX[sl][16] = s;
    }
    __syncthreads();
    float acc = sX[sl][16] * b1[q];
#pragma unroll
    for (int c = 0; c < 16; c++)
        acc = fmaf(sX[sl][c], sW1[c * 64 + q], acc);
    g_edge1[(size_t)slot * Hh + q] = acc * g_binv[slot];
}

// ---------------- layer 2 edge emb ----------------
__global__ void __launch_bounds__(256) k_es2(const float* __restrict__ W2,
                                             const float* __restrict__ b2) {
    __shared__ float sW2[64 * 64];
    __shared__ float sV[4][65];
    __shared__ float ss2[4];
    int tid = threadIdx.x;
    for (int j = tid; j < 4096; j += 256) sW2[j] = W2[j];
    int sl = tid >> 6, h = tid & 63;
    int slot = blockIdx.x * 4 + sl;
    int t = slot / Ee;
    int beg = g_offE[slot], end = g_offE[slot + 1];
    const float* e1base = g_edge1 + (size_t)t * Ee * Hh + h;
    float acc = 0.f;
    float s2 = 0.f;
    for (int j = beg; j < end; j++) {
        int n = g_elist[j];
        int sn = t * Nn + n;
        float d = __ldg(g_dinv + sn);
        float d2 = d * d;
        s2 += d;
        int nb = g_offN[sn], ne = g_offN[sn + 1];
        for (int jj = nb; jj < ne; jj++) {
            int ep = g_nlist[jj];
            acc = fmaf(d2, __ldg(e1base + (size_t)ep * Hh), acc);
        }
    }
    sV[sl][h] = acc;
    if (h == 0) ss2[sl] = s2;
    __syncthreads();
    float r = ss2[sl] * b2[h];
#pragma unroll 8
    for (int c = 0; c < 64; c++)
        r = fmaf(sV[sl][c], sW2[c * 64 + h], r);
    g_es[(size_t)slot * Hh + h] = r * g_binv[slot];
}

// ---------------- per-node heads ----------------
#define GN 8
#define CH 8
__global__ void __launch_bounds__(256) k_node(
        const float* __restrict__ nf,
        const float* __restrict__ bna,
        const float* __restrict__ Wt,  const float* __restrict__ bt,
        const float* __restrict__ Wr,  const float* __restrict__ br,
        const float* __restrict__ Wf,  const float* __restrict__ bf,
        float* __restrict__ out) {
    __shared__ float sx[GN][64][12];
    __shared__ u64 swc2[CH * 3 * 32];
    __shared__ float swt[3 * 192];
    __shared__ float swr[3 * 16];
    __shared__ float shv[GN][3][Tt];
    int tid = threadIdx.x;
    int g = tid >> 5, cp = tid & 31;
    int n = blockIdx.x * GN + g;

#pragma unroll
    for (int t = 0; t < Tt; t++) {
        int slot = t * Nn + n;
        int beg = g_offN[slot], end = g_offN[slot + 1];
        float d = g_dinv[slot];
        const float* src = g_es + (size_t)t * Ee * Hh;
        float a0 = 0.f, a1 = 0.f;
        for (int j = beg; j < end; j++) {
            const float* row = src + (size_t)g_nlist[j] * Hh;
            a0 += __ldg(row + cp);
            a1 += __ldg(row + cp + 32);
        }
        sx[g][cp][t]      = a0 * d;
        sx[g][cp + 32][t] = a1 * d;
    }
    for (int j = tid; j < 576; j += 256)
        swt[j] = Wt[(61 + j / 192) * 192 + (j % 192)];
    if (tid < 48) swr[tid] = Wr[(61 + tid / 16) * 16 + (tid % 16)];

    u64 acc2[9];
    {
        u64 b2 = pk2(bna[cp], bna[cp + 32]);
#pragma unroll
        for (int s = 0; s < 9; s++) acc2[s] = b2;
    }

    const u64* gw2 = (const u64*)g_wnat2;
    for (int chunk = 0; chunk < 64 / CH; chunk++) {
        __syncthreads();
        for (int j = tid; j < CH * 3 * 32; j += 256)
            swc2[j] = gw2[chunk * (CH * 3 * 32) + j];
        __syncthreads();
#pragma unroll
        for (int ii = 0; ii < CH; ii++) {
            int i = chunk * CH + ii;
            float4 x0 = *(const float4*)&sx[g][i][0];
            float4 x1 = *(const float4*)&sx[g][i][4];
            float4 x2 = *(const float4*)&sx[g][i][8];
            float xv[11] = {x0.x, x0.y, x0.z, x0.w, x1.x, x1.y, x1.z, x1.w,
                            x2.x, x2.y, x2.z};
            u64 xd[11];
#pragma unroll
            for (int s = 0; s < 11; s++) xd[s] = pk2(xv[s], xv[s]);
            u64 w0 = swc2[(ii * 3 + 0) * 32 + cp];
            u64 w1 = swc2[(ii * 3 + 1) * 32 + cp];
            u64 w2 = swc2[(ii * 3 + 2) * 32 + cp];
#pragma unroll
            for (int s = 0; s < 9; s++) {
                acc2[s] = fma2(w0, xd[s], acc2[s]);
                acc2[s] = fma2(w1, xd[s + 1], acc2[s]);
                acc2[s] = fma2(w2, xd[s + 2], acc2[s]);
            }
        }
    }
    {
        size_t b0 = ((size_t)cp * Nn + n) * 9;
        size_t b1 = ((size_t)(cp + 32) * Nn + n) * 9;
#pragma unroll
        for (int s = 0; s < 9; s++) {
            float lo, hi;
            upk2(lo, hi, acc2[s]);
            g_agg[b0 + s] = lo;
            g_agg[b1 + s] = hi;
        }
    }

    for (int u = tid; u < GN * 36; u += 256) {
        int gg = u / 36, r = u % 36;
        int o3 = r / Tt, t = r % Tt;
        int nn = blockIdx.x * GN + gg;
        float xp = bt[61 + o3];
#pragma unroll
        for (int dk = 0; dk < 3; dk++) {
            int tau = t + dk - 1;
            if (tau >= 0 && tau < Tt) {
                const float* wt = swt + o3 * 192 + dk;
#pragma unroll 8
                for (int i = 0; i < 64; i++) xp = fmaf(wt[i * 3], sx[gg][i][tau], xp);
            }
        }
        float rs = br[61 + o3];
        const float* xr = nf + ((size_t)t * Nn + nn) * CINc;
#pragma unroll
        for (int cc = 0; cc < CINc; cc++) rs = fmaf(swr[o3 * 16 + cc], xr[cc], rs);
        shv[gg][o3][t] = fmaxf(xp + rs, 0.f);
    }
    __syncthreads();
    if (tid < GN * Pp) {
        int gg = tid / Pp, pc = tid % Pp;
        int nn = blockIdx.x * GN + gg;
        float a = bf[pc];
#pragma unroll
        for (int t = 0; t < Tt; t++)
#pragma unroll
            for (int dk = 0; dk < 3; dk++)
                a = fmaf(Wf[pc * 36 + t * 3 + dk], shv[gg][dk][t], a);
        out[(size_t)nn * Pp + pc] = a;
    }
}

// ---------------- per-edge aggregator ----------------
__global__ void __launch_bounds__(256) k_eagg(const float* __restrict__ bea) {
    __shared__ float sx[GN][64][12];
    __shared__ u64 swc2[CH * 3 * 32];
    int tid = threadIdx.x;
    int g = tid >> 5, cp = tid & 31;
    int e = blockIdx.x * GN + g;

#pragma unroll
    for (int t = 0; t < 11; t++) {
        sx[g][cp][t]      = g_es[((size_t)t * Ee + e) * Hh + cp];
        sx[g][cp + 32][t] = g_es[((size_t)t * Ee + e) * Hh + cp + 32];
    }
    sx[g][cp][11] = 0.f;
    sx[g][cp + 32][11] = 0.f;

    u64 acc2[9];
    {
        u64 b2 = pk2(bea[cp], bea[cp + 32]);
#pragma unroll
        for (int s = 0; s < 9; s++) acc2[s] = b2;
    }

    const u64* gw2 = (const u64*)g_weat2;
    for (int chunk = 0; chunk < 64 / CH; chunk++) {
        __syncthreads();
        for (int j = tid; j < CH * 3 * 32; j += 256)
            swc2[j] = gw2[chunk * (CH * 3 * 32) + j];
        __syncthreads();
#pragma unroll
        for (int ii = 0; ii < CH; ii++) {
            int i = chunk * CH + ii;
            float4 x0 = *(const float4*)&sx[g][i][0];
            float4 x1 = *(const float4*)&sx[g][i][4];
            float4 x2 = *(const float4*)&sx[g][i][8];
            float xv[11] = {x0.x, x0.y, x0.z, x0.w, x1.x, x1.y, x1.z, x1.w,
                            x2.x, x2.y, x2.z};
            u64 xd[11];
#pragma unroll
            for (int s = 0; s < 11; s++) xd[s] = pk2(xv[s], xv[s]);
            u64 w0 = swc2[(ii * 3 + 0) * 32 + cp];
            u64 w1 = swc2[(ii * 3 + 1) * 32 + cp];
            u64 w2 = swc2[(ii * 3 + 2) * 32 + cp];
#pragma unroll
            for (int s = 0; s < 9; s++) {
                acc2[s] = fma2(w0, xd[s], acc2[s]);
                acc2[s] = fma2(w1, xd[s + 1], acc2[s]);
                acc2[s] = fma2(w2, xd[s + 2], acc2[s]);
            }
        }
    }
    size_t b0 = ((size_t)cp * Ee + e) * 9;
    size_t b1 = ((size_t)(cp + 32) * Ee + e) * 9;
#pragma unroll
    for (int s = 0; s < 9; s++) {
        float lo, hi;
        upk2(lo, hi, acc2[s]);
        g_eagg[b0 + s] = lo;
        g_eagg[b1 + s] = hi;
    }
}

// ---------------- score MLP: tf32 mma, 64 pairs x 64 h per block ----------------
__global__ void __launch_bounds__(128) k_mlp(
        const int* __restrict__ ni_full, const int* __restrict__ ei_full,
        const int* __restrict__ nni, const int* __restrict__ nei,
        const float* __restrict__ Wm1, const float* __restrict__ bm1,
        const float* __restrict__ Wm2, const float* __restrict__ bm2,
        float* __restrict__ out) {
    __shared__ unsigned zs[64][68];   // [pair][k] tf32, pad 68 -> conflict-free A lds
    __shared__ unsigned ws[64][68];   // [k][h] tf32
    __shared__ int sn[64], se[64];
    __shared__ float sbm1[64], swm2[64];
    int tid = threadIdx.x;
    int q0 = blockIdx.x * 64;
    if (tid < 64) {
        int q = q0 + tid;
        int n, e;
        if (q < NNZn) { n = ni_full[11 * NNZn + q]; e = ei_full[11 * NNZn + q]; }
        else          { n = nni[q - NNZn];          e = nei[q - NNZn]; }
        sn[tid] = n; se[tid] = e;
        sbm1[tid] = bm1[tid]; swm2[tid] = Wm2[tid];
    }
    __syncthreads();

    int w = tid >> 5;                 // warp 0..3 -> pair strip p0 = w*16
    int lane = tid & 31;
    int g = lane >> 2, tg = lane & 3;
    int p0 = w * 16;

    float acc[8][4];
#pragma unroll
    for (int nt = 0; nt < 8; nt++)
#pragma unroll
        for (int j = 0; j < 4; j++) acc[nt][j] = 0.f;

    const float4* ag4 = (const float4*)g_agg;
    const float4* eg4 = (const float4*)g_eagg;
    const float4* wm4 = (const float4*)Wm1;
    int p = tid & 63, half = tid >> 6;        // staging roles for zs
    int an = sn[p] * 144, ae = se[p] * 144;

    for (int c = 0; c < 9; c++) {
        __syncthreads();
        // stage Wm1 chunk [64k][64h] as tf32
        for (int j = tid; j < 1024; j += 128) {
            float4 v = wm4[c * 1024 + j];
            uint4 t4 = make_uint4(f2tf(v.x), f2tf(v.y), f2tf(v.z), f2tf(v.w));
            int k = j >> 4, h4 = j & 15;
            *(uint4*)&ws[k][h4 * 4] = t4;
        }
        // stage z = agg .* eagg for 64 pairs x 64 k (tf32)
        {
            int base = an + c * 16 + half * 8;
            int ebase = ae + c * 16 + half * 8;
#pragma unroll
            for (int j = 0; j < 8; j++) {
                float4 a = ag4[base + j];
                float4 b = eg4[ebase + j];
                uint4 t4 = make_uint4(f2tf(a.x * b.x), f2tf(a.y * b.y),
                                      f2tf(a.z * b.z), f2tf(a.w * b.w));
                *(uint4*)&zs[p][half * 32 + j * 4] = t4;
            }
        }
        __syncthreads();
#pragma unroll
        for (int s = 0; s < 8; s++) {
            int kk = s * 8;
            unsigned a0 = zs[p0 + g][kk + tg];
            unsigned a1 = zs[p0 + g + 8][kk + tg];
            unsigned a2 = zs[p0 + g][kk + tg + 4];
            unsigned a3 = zs[p0 + g + 8][kk + tg + 4];
#pragma unroll
            for (int nt = 0; nt < 8; nt++) {
                unsigned b0 = ws[kk + tg][nt * 8 + g];
                unsigned b1 = ws[kk + tg + 4][nt * 8 + g];
                mma_tf32(acc[nt][0], acc[nt][1], acc[nt][2], acc[nt][3],
                         a0, a1, a2, a3, b0, b1);
            }
        }
    }

    // epilogue: relu(+bm1) * Wm2, reduce over h (quad shuffle), write 2 rows/quad
    float sum0 = 0.f, sum1 = 0.f;
#pragma unroll
    for (int nt = 0; nt < 8; nt++) {
        int h0 = nt * 8 + 2 * tg;
        float b0 = sbm1[h0], b1 = sbm1[h0 + 1];
        float w0 = swm2[h0], w1 = swm2[h0 + 1];
        sum0 += fmaxf(acc[nt][0] + b0, 0.f) * w0 + fmaxf(acc[nt][1] + b1, 0.f) * w1;
        sum1 += fmaxf(acc[nt][2] + b0, 0.f) * w0 + fmaxf(acc[nt][3] + b1, 0.f) * w1;
    }
    sum0 += __shfl_xor_sync(0xffffffffu, sum0, 1);
    sum0 += __shfl_xor_sync(0xffffffffu, sum0, 2);
    sum1 += __shfl_xor_sync(0xffffffffu, sum1, 1);
    sum1 += __shfl_xor_sync(0xffffffffu, sum1, 2);
    if (tg == 0) {
        float bb = bm2[0];
        out[(size_t)Nn * Pp + q0 + p0 + g] = sum0 + bb;
        out[(size_t)Nn * Pp + q0 + p0 + g + 8] = sum1 + bb;
    }
}

// ---------------- host launcher ----------------
extern "C" void kernel_launch(void* const* d_in, const int* in_sizes, int n_in,
                              void* d_out, int out_size) {
    const float* nf  = (const float*)d_in[0];
    const float* W1  = (const float*)d_in[1];
    const float* b1  = (const float*)d_in[2];
    const float* W2  = (const float*)d_in[3];
    const float* b2  = (const float*)d_in[4];
    const float* Wt  = (const float*)d_in[5];
    const float* bt  = (const float*)d_in[6];
    const float* Wr  = (const float*)d_in[7];
    const float* br  = (const float*)d_in[8];
    const float* Wf  = (const float*)d_in[9];
    const float* bf  = (const float*)d_in[10];
    const float* Wna = (const float*)d_in[11];
    const float* bna = (const float*)d_in[12];
    const float* Wea = (const float*)d_in[13];
    const float* bea = (const float*)d_in[14];
    const float* Wm1 = (const float*)d_in[15];
    const float* bm1 = (const float*)d_in[16];
    const float* Wm2 = (const float*)d_in[17];
    const float* bm2 = (const float*)d_in[18];
    const int* node_idx = (const int*)d_in[19];
    const int* edge_idx = (const int*)d_in[20];
    const int* nni = (const int*)d_in[21];
    const int* nei = (const int*)d_in[22];
    float* out = (float*)d_out;

    int nbE = (TE + 4095) / 4096;
    int nbN = (TN + 4095) / 4096;

    k_zero<<<2048, 256>>>();
    k_count<<<(TNNZ + 255) / 256, 256>>>(node_idx, edge_idx);
    k_inv<<<(TN + 255) / 256, 256>>>();
    k_xd<<<(TN * 4 + 255) / 256, 256>>>(nf);
    k_scanA<0><<<nbE, 256>>>();
    k_scanB<<<1, 1024>>>(nbE);
    k_scanC<0><<<nbE, 256>>>();
    k_scanA<1><<<nbN, 256>>>();
    k_scanB<<<1, 1024>>>(nbN);
    k_scanC<1><<<nbN, 256>>>();
    k_fill<<<(TNNZ + 255) / 256, 256>>>(node_idx, edge_idx);
    k_prep<<<(192 * 64 + 255) / 256, 256>>>(Wna, Wea);

    k_e1<<<TE / 4, 256>>>(W1, b1);
    k_es2<<<TE / 4, 256>>>(W2, b2);

    k_node<<<Nn / GN, 256>>>(nf, bna, Wt, bt, Wr, br, Wf, bf, out);
    k_eagg<<<Ee / GN, 256>>>(bea);
    k_mlp<<<(2 * NNZn) / 64, 128>>>(node_idx, edge_idx, nni, nei, Wm1, bm1, Wm2, bm2, out);
}

// round 11
// speedup vs baseline: 4.3515x; 1.0910x over previous
#include <cuda_runtime.h>

#define Tt   12
#define Nn   100000
#define CINc 16
#define Ee   20000
#define NNZn 160000
#define Hh   64
#define Pp   12

#define TN   (Tt * Nn)
#define TE   (Tt * Ee)
#define TNNZ (Tt * NNZn)

typedef unsigned long long u64;

// ---- f32x2 packed helpers ----
__device__ __forceinline__ u64 pk2(float lo, float hi) {
    u64 r;
    asm("mov.b64 %0, {%1, %2};" : "=l"(r) : "f"(lo), "f"(hi));
    return r;
}
__device__ __forceinline__ void upk2(float& lo, float& hi, u64 v) {
    asm("mov.b64 {%0, %1}, %2;" : "=f"(lo), "=f"(hi) : "l"(v));
}
__device__ __forceinline__ u64 fma2(u64 a, u64 b, u64 c) {
    u64 d;
    asm("fma.rn.f32x2 %0, %1, %2, %3;" : "=l"(d) : "l"(a), "l"(b), "l"(c));
    return d;
}
// ---- tf32 helpers ----
__device__ __forceinline__ unsigned f2tf(float f) {
    unsigned r;
    asm("cvt.rna.tf32.f32 %0, %1;" : "=r"(r) : "f"(f));
    return r;
}
__device__ __forceinline__ void mma_tf32(float& c0, float& c1, float& c2, float& c3,
                                         unsigned a0, unsigned a1, unsigned a2, unsigned a3,
                                         unsigned b0, unsigned b1) {
    asm volatile(
        "mma.sync.aligned.m16n8k8.row.col.f32.tf32.tf32.f32 "
        "{%0,%1,%2,%3}, {%4,%5,%6,%7}, {%8,%9}, {%0,%1,%2,%3};"
        : "+f"(c0), "+f"(c1), "+f"(c2), "+f"(c3)
        : "r"(a0), "r"(a1), "r"(a2), "r"(a3), "r"(b0), "r"(b1));
}

// ---------------- scratch ----------------
__device__ float g_xd[(size_t)TN * CINc];
__device__ float g_es[(size_t)TE * Hh];
__device__ float g_edge1[(size_t)TE * Hh];
__device__ float g_agg[(size_t)Hh * Nn * 9];
__device__ float g_eagg[(size_t)Hh * Ee * 9];
__device__ float g_dinv[TN];
__device__ float g_binv[TE];
__device__ float g_wnat2[192 * 64];
__device__ float g_weat2[192 * 64];
__device__ uint4 g_wm1tf4[576 * 64 / 4];   // Wm1 pre-converted to tf32 bits

__device__ int g_degN[TN];
__device__ int g_degE[TE];
__device__ int g_offN[TN + 1];
__device__ int g_offE[TE + 1];
__device__ int g_curN[TN];
__device__ int g_curE[TE];
__device__ int g_nlist[TNNZ];
__device__ int g_elist[TNNZ];
__device__ int g_part[1024];

// ---------------- zero ----------------
__global__ void k_zero() {
    int i = blockIdx.x * blockDim.x + threadIdx.x;
    int stride = gridDim.x * blockDim.x;
    for (int j = i; j < TN; j += stride) { g_degN[j] = 0; g_curN[j] = 0; }
    for (int j = i; j < TE; j += stride) { g_degE[j] = 0; g_curE[j] = 0; }
}

__global__ void k_count(const int* __restrict__ ni, const int* __restrict__ ei) {
    int i = blockIdx.x * blockDim.x + threadIdx.x;
    if (i >= TNNZ) return;
    int t = i / NNZn;
    atomicAdd(&g_degN[t * Nn + ni[i]], 1);
    atomicAdd(&g_degE[t * Ee + ei[i]], 1);
}

__global__ void k_inv() {
    int i = blockIdx.x * blockDim.x + threadIdx.x;
    if (i < TN) { int d = g_degN[i]; g_dinv[i] = d > 0 ? rsqrtf((float)d) : 0.f; }
    if (i < TE) { int c = g_degE[i]; g_binv[i] = c > 0 ? 1.f / (float)c : 0.f; }
}

// ---------------- xd = x * dinv ----------------
__global__ void k_xd(const float* __restrict__ nf) {
    int gi = blockIdx.x * blockDim.x + threadIdx.x;
    if (gi >= TN * 4) return;
    int u = gi >> 2, q = gi & 3;
    float d = g_dinv[u];
    float4 v = ((const float4*)nf)[(size_t)u * 4 + q];
    v.x *= d; v.y *= d; v.z *= d; v.w *= d;
    ((float4*)g_xd)[(size_t)u * 4 + q] = v;
}

// ---------------- scans ----------------
template <int SEL>
__global__ void k_scanA() {
    const int* cnt = SEL ? g_degN : g_degE;
    const int n = SEL ? TN : TE;
    __shared__ int sh[256];
    int b = blockIdx.x, t = threadIdx.x;
    int i0 = b * 4096 + t * 16;
    int s = 0;
#pragma unroll
    for (int k = 0; k < 16; k++) { int i = i0 + k; if (i < n) s += cnt[i]; }
    sh[t] = s; __syncthreads();
    for (int off = 128; off; off >>= 1) {
        if (t < off) sh[t] += sh[t + off];
        __syncthreads();
    }
    if (t == 0) g_part[b] = sh[0];
}

__global__ void k_scanB(int nb) {
    __shared__ int sh[1024];
    int t = threadIdx.x;
    int v = (t < nb) ? g_part[t] : 0;
    sh[t] = v; __syncthreads();
    for (int off = 1; off < 1024; off <<= 1) {
        int a = (t >= off) ? sh[t - off] : 0;
        __syncthreads();
        sh[t] += a;
        __syncthreads();
    }
    if (t < nb) g_part[t] = sh[t] - v;
}

template <int SEL>
__global__ void k_scanC() {
    const int* cnt = SEL ? g_degN : g_degE;
    int* off = SEL ? g_offN : g_offE;
    const int n = SEL ? TN : TE;
    __shared__ int sh[256];
    int b = blockIdx.x, t = threadIdx.x;
    int i0 = b * 4096 + t * 16;
    int loc[16]; int s = 0;
#pragma unroll
    for (int k = 0; k < 16; k++) {
        int i = i0 + k;
        loc[k] = (i < n) ? cnt[i] : 0;
        s += loc[k];
    }
    sh[t] = s; __syncthreads();
    for (int o = 1; o < 256; o <<= 1) {
        int a = (t >= o) ? sh[t - o] : 0;
        __syncthreads();
        sh[t] += a;
        __syncthreads();
    }
    int run = g_part[b] + sh[t] - s;
#pragma unroll
    for (int k = 0; k < 16; k++) {
        int i = i0 + k;
        if (i < n) {
            off[i] = run;
            run += loc[k];
            if (i == n - 1) off[n] = run;
        }
    }
}

__global__ void k_fill(const int* __restrict__ ni, const int* __restrict__ ei) {
    int i = blockIdx.x * blockDim.x + threadIdx.x;
    if (i >= TNNZ) return;
    int t = i / NNZn;
    int n = ni[i], e = ei[i];
    int se = t * Ee + e, sn = t * Nn + n;
    int pe = atomicAdd(&g_curE[se], 1);
    g_elist[g_offE[se] + pe] = n;
    int pn = atomicAdd(&g_curN[sn], 1);
    g_nlist[g_offN[sn] + pn] = e;
}

// ---------------- weight prep ----------------
__global__ void k_prep(const float* __restrict__ Wna, const float* __restrict__ Wea,
                       const float* __restrict__ Wm1) {
    int i = blockIdx.x * blockDim.x + threadIdx.x;
    if (i < 192 * 64) {
        int c = i / 192, i3 = i % 192;
        int cp = c & 31, hi = c >> 5;
        g_wnat2[(i3 * 32 + cp) * 2 + hi] = Wna[i];
        g_weat2[(i3 * 32 + cp) * 2 + hi] = Wea[i];
    }
    if (i < 576 * 64)
        ((unsigned*)g_wm1tf4)[i] = f2tf(Wm1[i]);
}

// ---------------- layer 1 edge emb: 16 slots/block ----------------
__global__ void __launch_bounds__(256) k_e1(const float* __restrict__ W1,
                                            const float* __restrict__ b1) {
    __shared__ float sW1[16 * 64];
    __shared__ float sX[4][17];
    int tid = threadIdx.x;
    for (int j = tid; j < 1024; j += 256) sW1[j] = W1[j];
    int sl = tid >> 6, q = tid & 63;
#pragma unroll
    for (int ss = 0; ss < 4; ss++) {
        int slot = blockIdx.x * 16 + ss * 4 + sl;
        int t = slot / Ee;
        int beg = g_offE[slot], end = g_offE[slot + 1];
        float a = 0.f;
        if (q < 16) {
            for (int j = beg; j < end; j++)
                a += __ldg(g_xd + (size_t)(t * Nn + g_elist[j]) * 16 + q);
        } else if (q == 16) {
            for (int j = beg; j < end; j++)
                a += __ldg(g_dinv + t * Nn + g_elist[j]);
        }
        __syncthreads();
        if (q <= 16) sX[sl][q] = a;
        __syncthreads();
        float acc = sX[sl][16] * b1[q];
#pragma unroll
        for (int c = 0; c < 16; c++)
            acc = fmaf(sX[sl][c], sW1[c * 64 + q], acc);
        g_edge1[(size_t)slot * Hh + q] = acc * g_binv[slot];
    }
}

// ---------------- layer 2 edge emb: 16 slots/block ----------------
__global__ void __launch_bounds__(256) k_es2(const float* __restrict__ W2,
                                             const float* __restrict__ b2) {
    __shared__ float sW2[64 * 64];
    __shared__ float sV[4][65];
    __shared__ float ss2[4];
    int tid = threadIdx.x;
    for (int j = tid; j < 4096; j += 256) sW2[j] = W2[j];
    int sl = tid >> 6, h = tid & 63;
#pragma unroll
    for (int ss = 0; ss < 4; ss++) {
        int slot = blockIdx.x * 16 + ss * 4 + sl;
        int t = slot / Ee;
        int beg = g_offE[slot], end = g_offE[slot + 1];
        const float* e1base = g_edge1 + (size_t)t * Ee * Hh + h;
        float acc = 0.f;
        float s2 = 0.f;
        for (int j = beg; j < end; j++) {
            int n = g_elist[j];
            int sn = t * Nn + n;
            float d = __ldg(g_dinv + sn);
            float d2 = d * d;
            s2 += d;
            int nb = g_offN[sn], ne = g_offN[sn + 1];
            for (int jj = nb; jj < ne; jj++) {
                int ep = g_nlist[jj];
                acc = fmaf(d2, __ldg(e1base + (size_t)ep * Hh), acc);
            }
        }
        __syncthreads();
        sV[sl][h] = acc;
        if (h == 0) ss2[sl] = s2;
        __syncthreads();
        float r = ss2[sl] * b2[h];
#pragma unroll 8
        for (int c = 0; c < 64; c++)
            r = fmaf(sV[sl][c], sW2[c * 64 + h], r);
        g_es[(size_t)slot * Hh + h] = r * g_binv[slot];
    }
}

// ---------------- per-node heads ----------------
#define GN 8
#define CH 8
__global__ void __launch_bounds__(256) k_node(
        const float* __restrict__ nf,
        const float* __restrict__ bna,
        const float* __restrict__ Wt,  const float* __restrict__ bt,
        const float* __restrict__ Wr,  const float* __restrict__ br,
        const float* __restrict__ Wf,  const float* __restrict__ bf,
        float* __restrict__ out) {
    __shared__ float sx[GN][64][12];
    __shared__ u64 swc2[CH * 3 * 32];
    __shared__ float swt[3 * 192];
    __shared__ float swr[3 * 16];
    __shared__ float shv[GN][3][Tt];
    int tid = threadIdx.x;
    int g = tid >> 5, cp = tid & 31;
    int n = blockIdx.x * GN + g;

#pragma unroll
    for (int t = 0; t < Tt; t++) {
        int slot = t * Nn + n;
        int beg = g_offN[slot], end = g_offN[slot + 1];
        float d = g_dinv[slot];
        const float* src = g_es + (size_t)t * Ee * Hh;
        float a0 = 0.f, a1 = 0.f;
        for (int j = beg; j < end; j++) {
            const float* row = src + (size_t)g_nlist[j] * Hh;
            a0 += __ldg(row + cp);
            a1 += __ldg(row + cp + 32);
        }
        sx[g][cp][t]      = a0 * d;
        sx[g][cp + 32][t] = a1 * d;
    }
    for (int j = tid; j < 576; j += 256)
        swt[j] = Wt[(61 + j / 192) * 192 + (j % 192)];
    if (tid < 48) swr[tid] = Wr[(61 + tid / 16) * 16 + (tid % 16)];

    u64 acc2[9];
    {
        u64 b2 = pk2(bna[cp], bna[cp + 32]);
#pragma unroll
        for (int s = 0; s < 9; s++) acc2[s] = b2;
    }

    const u64* gw2 = (const u64*)g_wnat2;
    for (int chunk = 0; chunk < 64 / CH; chunk++) {
        __syncthreads();
        for (int j = tid; j < CH * 3 * 32; j += 256)
            swc2[j] = gw2[chunk * (CH * 3 * 32) + j];
        __syncthreads();
#pragma unroll
        for (int ii = 0; ii < CH; ii++) {
            int i = chunk * CH + ii;
            float4 x0 = *(const float4*)&sx[g][i][0];
            float4 x1 = *(const float4*)&sx[g][i][4];
            float4 x2 = *(const float4*)&sx[g][i][8];
            float xv[11] = {x0.x, x0.y, x0.z, x0.w, x1.x, x1.y, x1.z, x1.w,
                            x2.x, x2.y, x2.z};
            u64 xd[11];
#pragma unroll
            for (int s = 0; s < 11; s++) xd[s] = pk2(xv[s], xv[s]);
            u64 w0 = swc2[(ii * 3 + 0) * 32 + cp];
            u64 w1 = swc2[(ii * 3 + 1) * 32 + cp];
            u64 w2 = swc2[(ii * 3 + 2) * 32 + cp];
#pragma unroll
            for (int s = 0; s < 9; s++) {
                acc2[s] = fma2(w0, xd[s], acc2[s]);
                acc2[s] = fma2(w1, xd[s + 1], acc2[s]);
                acc2[s] = fma2(w2, xd[s + 2], acc2[s]);
            }
        }
    }
    {
        size_t b0 = ((size_t)cp * Nn + n) * 9;
        size_t b1 = ((size_t)(cp + 32) * Nn + n) * 9;
#pragma unroll
        for (int s = 0; s < 9; s++) {
            float lo, hi;
            upk2(lo, hi, acc2[s]);
            g_agg[b0 + s] = lo;
            g_agg[b1 + s] = hi;
        }
    }

    for (int u = tid; u < GN * 36; u += 256) {
        int gg = u / 36, r = u % 36;
        int o3 = r / Tt, t = r % Tt;
        int nn = blockIdx.x * GN + gg;
        float xp = bt[61 + o3];
#pragma unroll
        for (int dk = 0; dk < 3; dk++) {
            int tau = t + dk - 1;
            if (tau >= 0 && tau < Tt) {
                const float* wt = swt + o3 * 192 + dk;
#pragma unroll 8
                for (int i = 0; i < 64; i++) xp = fmaf(wt[i * 3], sx[gg][i][tau], xp);
            }
        }
        float rs = br[61 + o3];
        const float* xr = nf + ((size_t)t * Nn + nn) * CINc;
#pragma unroll
        for (int cc = 0; cc < CINc; cc++) rs = fmaf(swr[o3 * 16 + cc], xr[cc], rs);
        shv[gg][o3][t] = fmaxf(xp + rs, 0.f);
    }
    __syncthreads();
    if (tid < GN * Pp) {
        int gg = tid / Pp, pc = tid % Pp;
        int nn = blockIdx.x * GN + gg;
        float a = bf[pc];
#pragma unroll
        for (int t = 0; t < Tt; t++)
#pragma unroll
            for (int dk = 0; dk < 3; dk++)
                a = fmaf(Wf[pc * 36 + t * 3 + dk], shv[gg][dk][t], a);
        out[(size_t)nn * Pp + pc] = a;
    }
}

// ---------------- per-edge aggregator ----------------
__global__ void __launch_bounds__(256) k_eagg(const float* __restrict__ bea) {
    __shared__ float sx[GN][64][12];
    __shared__ u64 swc2[CH * 3 * 32];
    int tid = threadIdx.x;
    int g = tid >> 5, cp = tid & 31;
    int e = blockIdx.x * GN + g;

#pragma unroll
    for (int t = 0; t < 11; t++) {
        sx[g][cp][t]      = g_es[((size_t)t * Ee + e) * Hh + cp];
        sx[g][cp + 32][t] = g_es[((size_t)t * Ee + e) * Hh + cp + 32];
    }
    sx[g][cp][11] = 0.f;
    sx[g][cp + 32][11] = 0.f;

    u64 acc2[9];
    {
        u64 b2 = pk2(bea[cp], bea[cp + 32]);
#pragma unroll
        for (int s = 0; s < 9; s++) acc2[s] = b2;
    }

    const u64* gw2 = (const u64*)g_weat2;
    for (int chunk = 0; chunk < 64 / CH; chunk++) {
        __syncthreads();
        for (int j = tid; j < CH * 3 * 32; j += 256)
            swc2[j] = gw2[chunk * (CH * 3 * 32) + j];
        __syncthreads();
#pragma unroll
        for (int ii = 0; ii < CH; ii++) {
            int i = chunk * CH + ii;
            float4 x0 = *(const float4*)&sx[g][i][0];
            float4 x1 = *(const float4*)&sx[g][i][4];
            float4 x2 = *(const float4*)&sx[g][i][8];
            float xv[11] = {x0.x, x0.y, x0.z, x0.w, x1.x, x1.y, x1.z, x1.w,
                            x2.x, x2.y, x2.z};
            u64 xd[11];
#pragma unroll
            for (int s = 0; s < 11; s++) xd[s] = pk2(xv[s], xv[s]);
            u64 w0 = swc2[(ii * 3 + 0) * 32 + cp];
            u64 w1 = swc2[(ii * 3 + 1) * 32 + cp];
            u64 w2 = swc2[(ii * 3 + 2) * 32 + cp];
#pragma unroll
            for (int s = 0; s < 9; s++) {
                acc2[s] = fma2(w0, xd[s], acc2[s]);
                acc2[s] = fma2(w1, xd[s + 1], acc2[s]);
                acc2[s] = fma2(w2, xd[s + 2], acc2[s]);
            }
        }
    }
    size_t b0 = ((size_t)cp * Ee + e) * 9;
    size_t b1 = ((size_t)(cp + 32) * Ee + e) * 9;
#pragma unroll
    for (int s = 0; s < 9; s++) {
        float lo, hi;
        upk2(lo, hi, acc2[s]);
        g_eagg[b0 + s] = lo;
        g_eagg[b1 + s] = hi;
    }
}

// ---------------- score MLP: tf32 mma, 128 pairs x 64 h per block, 256 thr ----------------
__global__ void __launch_bounds__(256) k_mlp(
        const int* __restrict__ ni_full, const int* __restrict__ ei_full,
        const int* __restrict__ nni, const int* __restrict__ nei,
        const float* __restrict__ bm1,
        const float* __restrict__ Wm2, const float* __restrict__ bm2,
        float* __restrict__ out) {
    __shared__ unsigned zs[128][36];   // [pair][k-chunk32], pad 36
    __shared__ unsigned ws[32][68];    // [k][h] — 64 h + pad 4 (R10 bug: was [32][36])
    __shared__ int sn[128], se[128];
    __shared__ float sbm1[64], swm2[64];
    int tid = threadIdx.x;
    int q0 = blockIdx.x * 128;
    if (tid < 128) {
        int q = q0 + tid;
        int n, e;
        if (q < NNZn) { n = ni_full[11 * NNZn + q]; e = ei_full[11 * NNZn + q]; }
        else          { n = nni[q - NNZn];          e = nei[q - NNZn]; }
        sn[tid] = n; se[tid] = e;
    }
    if (tid < 64) { sbm1[tid] = bm1[tid]; swm2[tid] = Wm2[tid]; }
    __syncthreads();

    int w = tid >> 5;                 // warp 0..7 -> pair strip p0 = w*16
    int lane = tid & 31;
    int g = lane >> 2, tg = lane & 3;
    int p0 = w * 16;

    float acc[8][4];
#pragma unroll
    for (int nt = 0; nt < 8; nt++)
#pragma unroll
        for (int j = 0; j < 4; j++) acc[nt][j] = 0.f;

    const float4* ag4 = (const float4*)g_agg;
    const float4* eg4 = (const float4*)g_eagg;
    int p = tid & 127, half = tid >> 7;    // staging: each (p,half) stages 16 k
    int an = sn[p] * 144, ae = se[p] * 144;

    for (int c = 0; c < 18; c++) {         // 18 chunks of 32 k
        __syncthreads();
        // stage weights (pre-converted tf32): 32k x 64h = 512 uint4
        for (int j = tid; j < 512; j += 256) {
            uint4 t4 = g_wm1tf4[c * 512 + j];
            int k = j >> 4, h4 = j & 15;
            *(uint4*)&ws[k][h4 * 4] = t4;
        }
        // stage z = agg .* eagg (tf32): 16 k per (p,half)
        {
            int base = an + c * 8 + half * 4;
            int ebase = ae + c * 8 + half * 4;
#pragma unroll
            for (int j = 0; j < 4; j++) {
                float4 a = ag4[base + j];
                float4 b = eg4[ebase + j];
                uint4 t4 = make_uint4(f2tf(a.x * b.x), f2tf(a.y * b.y),
                                      f2tf(a.z * b.z), f2tf(a.w * b.w));
                *(uint4*)&zs[p][half * 16 + j * 4] = t4;
            }
        }
        __syncthreads();
#pragma unroll
        for (int s = 0; s < 4; s++) {
            int kk = s * 8;
            unsigned a0 = zs[p0 + g][kk + tg];
            unsigned a1 = zs[p0 + g + 8][kk + tg];
            unsigned a2 = zs[p0 + g][kk + tg + 4];
            unsigned a3 = zs[p0 + g + 8][kk + tg + 4];
#pragma unroll
            for (int nt = 0; nt < 8; nt++) {
                unsigned b0 = ws[kk + tg][nt * 8 + g];
                unsigned b1 = ws[kk + tg + 4][nt * 8 + g];
                mma_tf32(acc[nt][0], acc[nt][1], acc[nt][2], acc[nt][3],
                         a0, a1, a2, a3, b0, b1);
            }
        }
    }

    // epilogue: relu(+bm1) * Wm2, quad shuffle-reduce over h
    float sum0 = 0.f, sum1 = 0.f;
#pragma unroll
    for (int nt = 0; nt < 8; nt++) {
        int h0 = nt * 8 + 2 * tg;
        float b0 = sbm1[h0], b1 = sbm1[h0 + 1];
        float w0 = swm2[h0], w1 = swm2[h0 + 1];
        sum0 += fmaxf(acc[nt][0] + b0, 0.f) * w0 + fmaxf(acc[nt][1] + b1, 0.f) * w1;
        sum1 += fmaxf(acc[nt][2] + b0, 0.f) * w0 + fmaxf(acc[nt][3] + b1, 0.f) * w1;
    }
    sum0 += __shfl_xor_sync(0xffffffffu, sum0, 1);
    sum0 += __shfl_xor_sync(0xffffffffu, sum0, 2);
    sum1 += __shfl_xor_sync(0xffffffffu, sum1, 1);
    sum1 += __shfl_xor_sync(0xffffffffu, sum1, 2);
    if (tg == 0) {
        float bb = bm2[0];
        out[(size_t)Nn * Pp + q0 + p0 + g] = sum0 + bb;
        out[(size_t)Nn * Pp + q0 + p0 + g + 8] = sum1 + bb;
    }
}

// ---------------- host launcher ----------------
extern "C" void kernel_launch(void* const* d_in, const int* in_sizes, int n_in,
                              void* d_out, int out_size) {
    const float* nf  = (const float*)d_in[0];
    const float* W1  = (const float*)d_in[1];
    const float* b1  = (const float*)d_in[2];
    const float* W2  = (const float*)d_in[3];
    const float* b2  = (const float*)d_in[4];
    const float* Wt  = (const float*)d_in[5];
    const float* bt  = (const float*)d_in[6];
    const float* Wr  = (const float*)d_in[7];
    const float* br  = (const float*)d_in[8];
    const float* Wf  = (const float*)d_in[9];
    const float* bf  = (const float*)d_in[10];
    const float* Wna = (const float*)d_in[11];
    const float* bna = (const float*)d_in[12];
    const float* Wea = (const float*)d_in[13];
    const float* bea = (const float*)d_in[14];
    const float* Wm1 = (const float*)d_in[15];
    const float* bm1 = (const float*)d_in[16];
    const float* Wm2 = (const float*)d_in[17];
    const float* bm2 = (const float*)d_in[18];
    const int* node_idx = (const int*)d_in[19];
    const int* edge_idx = (const int*)d_in[20];
    const int* nni = (const int*)d_in[21];
    const int* nei = (const int*)d_in[22];
    float* out = (float*)d_out;

    int nbE = (TE + 4095) / 4096;
    int nbN = (TN + 4095) / 4096;

    k_zero<<<2048, 256>>>();
    k_count<<<(TNNZ + 255) / 256, 256>>>(node_idx, edge_idx);
    k_inv<<<(TN + 255) / 256, 256>>>();
    k_xd<<<(TN * 4 + 255) / 256, 256>>>(nf);
    k_scanA<0><<<nbE, 256>>>();
    k_scanB<<<1, 1024>>>(nbE);
    k_scanC<0><<<nbE, 256>>>();
    k_scanA<1><<<nbN, 256>>>();
    k_scanB<<<1, 1024>>>(nbN);
    k_scanC<1><<<nbN, 256>>>();
    k_fill<<<(TNNZ + 255) / 256, 256>>>(node_idx, edge_idx);
    k_prep<<<(576 * 64 + 255) / 256, 256>>>(Wna, Wea, Wm1);

    k_e1<<<TE / 16, 256>>>(W1, b1);
    k_es2<<<TE / 16, 256>>>(W2, b2);

    k_node<<<Nn / GN, 256>>>(nf, bna, Wt, bt, Wr, br, Wf, bf, out);
    k_eagg<<<Ee / GN, 256>>>(bea);
    k_mlp<<<(2 * NNZn) / 128, 256>>>(node_idx, edge_idx, nni, nei, bm1, Wm2, bm2, out);
}